// round 4
// baseline (speedup 1.0000x reference)
#include <cuda_runtime.h>
#include <cuda_bf16.h>
#include <cstdint>

// ---------------------------------------------------------------------------
// BEEncdecMultiheadAttn: Tq=Tk=1024, B=8, H=1024, heads=16, hd=64
// Round 4: mma.sync bf16 3-term everywhere; multi-stage cp.async pipelines
// (GEMM: 4 stages, 1 sync/chunk; attention: 3 stages, 1 sync/iter).
// ---------------------------------------------------------------------------

namespace {
constexpr int TQ = 1024, TK = 1024, B = 8, H = 1024, K = 1024;
}

__device__ __nv_bfloat16 g_aq_h [B * TQ * H], g_aq_l [B * TQ * H];
__device__ __nv_bfloat16 g_akv_h[B * TK * H], g_akv_l[B * TK * H];
__device__ __nv_bfloat16 g_wq_h [H * H],      g_wq_l [H * H];
__device__ __nv_bfloat16 g_wkv_h[2 * H * H],  g_wkv_l[2 * H * H];
__device__ __nv_bfloat16 g_wo_h [H * H],      g_wo_l [H * H];
__device__ __nv_bfloat16 g_qh [B * TQ * H],      g_ql [B * TQ * H];       // [b][t][H]
__device__ __nv_bfloat16 g_kvh[B * TK * 2 * H],  g_kvl[B * TK * 2 * H];   // [b][t][2H]
__device__ __nv_bfloat16 g_cxh[TQ * B * H],      g_cxl[TQ * B * H];       // [t][b][H]

// ---------------------------------------------------------------------------
// helpers (sm_80+ baseline PTX only)
// ---------------------------------------------------------------------------
__device__ __forceinline__ uint32_t smem_u32(const void* p) {
    uint32_t a;
    asm("{ .reg .u64 t; cvta.to.shared.u64 t, %1; cvt.u32.u64 %0, t; }" : "=r"(a) : "l"(p));
    return a;
}
__device__ __forceinline__ void cpa16(uint32_t dst, const void* src) {
    asm volatile("cp.async.cg.shared.global [%0], [%1], 16;" :: "r"(dst), "l"(src));
}
__device__ __forceinline__ void cpa_commit() { asm volatile("cp.async.commit_group;" ::: "memory"); }
template <int N>
__device__ __forceinline__ void cpa_wait() { asm volatile("cp.async.wait_group %0;" :: "n"(N) : "memory"); }

__device__ __forceinline__ void ldsm4(uint32_t r[4], uint32_t addr) {
    asm volatile("ldmatrix.sync.aligned.m8n8.x4.shared.b16 {%0,%1,%2,%3}, [%4];"
                 : "=r"(r[0]), "=r"(r[1]), "=r"(r[2]), "=r"(r[3]) : "r"(addr));
}
__device__ __forceinline__ void ldsm4t(uint32_t r[4], uint32_t addr) {
    asm volatile("ldmatrix.sync.aligned.m8n8.x4.trans.shared.b16 {%0,%1,%2,%3}, [%4];"
                 : "=r"(r[0]), "=r"(r[1]), "=r"(r[2]), "=r"(r[3]) : "r"(addr));
}
__device__ __forceinline__ void mma16816(float c[4], const uint32_t a[4], uint32_t b0, uint32_t b1) {
    asm volatile(
        "mma.sync.aligned.m16n8k16.row.col.f32.bf16.bf16.f32 "
        "{%0,%1,%2,%3}, {%4,%5,%6,%7}, {%8,%9}, {%0,%1,%2,%3};"
        : "+f"(c[0]), "+f"(c[1]), "+f"(c[2]), "+f"(c[3])
        : "r"(a[0]), "r"(a[1]), "r"(a[2]), "r"(a[3]), "r"(b0), "r"(b1));
}
__device__ __forceinline__ float ex2(float x) {
    float y; asm("ex2.approx.ftz.f32 %0, %1;" : "=f"(y) : "f"(x)); return y;
}
__device__ __forceinline__ uint32_t pack_bf2(__nv_bfloat16 x, __nv_bfloat16 y) {
    __nv_bfloat162 t = __halves2bfloat162(x, y);
    return *reinterpret_cast<uint32_t*>(&t);
}
__device__ __forceinline__ void pack_hilo(float a, float b, uint32_t& h, uint32_t& l) {
    __nv_bfloat16 ha = __float2bfloat16_rn(a), hb = __float2bfloat16_rn(b);
    __nv_bfloat16 la = __float2bfloat16_rn(a - __bfloat162float(ha));
    __nv_bfloat16 lb = __float2bfloat16_rn(b - __bfloat162float(hb));
    h = pack_bf2(ha, hb);
    l = pack_bf2(la, lb);
}
__device__ __forceinline__ void split2(float x, __nv_bfloat16& h, __nv_bfloat16& l) {
    h = __float2bfloat16_rn(x);
    l = __float2bfloat16_rn(x - __bfloat162float(h));
}

// ---------------------------------------------------------------------------
// split kernels
// ---------------------------------------------------------------------------
__global__ __launch_bounds__(256) void split_act_kernel(
    const float* __restrict__ x, const float* __restrict__ r,
    __nv_bfloat16* __restrict__ hi, __nv_bfloat16* __restrict__ lo, int T)
{
    const int i = blockIdx.x * blockDim.x + threadIdx.x;
    if (i >= T * B * H / 4) return;
    const int e = i * 4, h = e % H, tb = e / H, b = tb % B, t = tb / B;
    float4 xv = ((const float4*)x)[i];
    float4 rv = *(const float4*)(r + b * H + h);
    xv.x *= rv.x; xv.y *= rv.y; xv.z *= rv.z; xv.w *= rv.w;
    __nv_bfloat16 h0, h1, h2, h3, l0, l1, l2, l3;
    split2(xv.x, h0, l0); split2(xv.y, h1, l1); split2(xv.z, h2, l2); split2(xv.w, h3, l3);
    const size_t o = ((size_t)b * T + t) * H + h;
    *(__nv_bfloat162*)(hi + o)     = __halves2bfloat162(h0, h1);
    *(__nv_bfloat162*)(hi + o + 2) = __halves2bfloat162(h2, h3);
    *(__nv_bfloat162*)(lo + o)     = __halves2bfloat162(l0, l1);
    *(__nv_bfloat162*)(lo + o + 2) = __halves2bfloat162(l2, l3);
}

// all three weight matrices in one launch
__global__ __launch_bounds__(256) void split_weights_kernel(
    const float* __restrict__ wq, const float* __restrict__ wkv, const float* __restrict__ wo,
    __nv_bfloat16* __restrict__ qh, __nv_bfloat16* __restrict__ ql,
    __nv_bfloat16* __restrict__ kh, __nv_bfloat16* __restrict__ kl,
    __nv_bfloat16* __restrict__ oh, __nv_bfloat16* __restrict__ ol)
{
    const int i = blockIdx.x * blockDim.x + threadIdx.x;   // f4 index over 1M
    constexpr int NQ = H * H / 4, NKV = 2 * H * H / 4;
    const float* src; __nv_bfloat16 *hi, *lo; int j;
    if (i < NQ)            { src = wq;  hi = qh; lo = ql; j = i; }
    else if (i < NQ + NKV) { src = wkv; hi = kh; lo = kl; j = i - NQ; }
    else                   { src = wo;  hi = oh; lo = ol; j = i - NQ - NKV; }
    float4 xv = ((const float4*)src)[j];
    __nv_bfloat16 h0, h1, h2, h3, l0, l1, l2, l3;
    split2(xv.x, h0, l0); split2(xv.y, h1, l1); split2(xv.z, h2, l2); split2(xv.w, h3, l3);
    const size_t o = (size_t)j * 4;
    *(__nv_bfloat162*)(hi + o)     = __halves2bfloat162(h0, h1);
    *(__nv_bfloat162*)(hi + o + 2) = __halves2bfloat162(h2, h3);
    *(__nv_bfloat162*)(lo + o)     = __halves2bfloat162(l0, l1);
    *(__nv_bfloat162*)(lo + o + 2) = __halves2bfloat162(l2, l3);
}

// ---------------------------------------------------------------------------
// GEMM: C = (Ah+Al)(Wh+Wl)^T (3-term), then *s[n] + bias[n].
// 128x128 tile, K-chunk 32, 4-stage cp.async pipeline, 8 warps (2m x 4n),
// one __syncthreads per chunk. smem row stride 80B (32 bf16 + 16B pad).
// ---------------------------------------------------------------------------
namespace {
constexpr int GSTR = 80;                 // row stride bytes
constexpr int GTILE = 128 * GSTR;        // 10240
constexpr int GSTAGE = 4 * GTILE;        // Ah, Al, Wh, Wl = 40960
constexpr int GEMM_SMEM = 4 * GSTAGE;    // 163840
constexpr int NCH = 32;                  // K / 32
}

__global__ __launch_bounds__(256) void gemm_mma_kernel(
    const __nv_bfloat16* __restrict__ ah, const __nv_bfloat16* __restrict__ al,
    const __nv_bfloat16* __restrict__ wh, const __nv_bfloat16* __restrict__ wl,
    int Mb,
    float* __restrict__ Cf, __nv_bfloat16* __restrict__ Chi, __nv_bfloat16* __restrict__ Clo,
    int ldc, long long strideCb,
    const float* __restrict__ svec, int sStride, const float* __restrict__ bias)
{
    extern __shared__ char smraw[];
    const uint32_t sb = smem_u32(smraw);

    const int tid = threadIdx.x, lane = tid & 31, wid = tid >> 5;
    const int wm = wid & 1, wn = wid >> 1;
    const int n0 = blockIdx.x * 128, m0 = blockIdx.y * 128, z = blockIdx.z;

    const __nv_bfloat16* Ah = ah + (size_t)z * Mb * K + (size_t)m0 * K;
    const __nv_bfloat16* Al = al + (size_t)z * Mb * K + (size_t)m0 * K;
    const __nv_bfloat16* Wh = wh + (size_t)n0 * K;
    const __nv_bfloat16* Wl = wl + (size_t)n0 * K;

    float acc[4][4][4];
#pragma unroll
    for (int a = 0; a < 4; a++)
#pragma unroll
        for (int b = 0; b < 4; b++)
#pragma unroll
            for (int c = 0; c < 4; c++) acc[a][b][c] = 0.f;

    // per-thread fixed load slot: 2 ops per array per chunk
    const int lrow = tid >> 2, lcol = tid & 3;          // rows 0..63(+64), col16 0..3
    auto issue_chunk = [&](int c, int st) {
        const uint32_t base = sb + st * GSTAGE;
        const size_t go = (size_t)c * 32;
        const __nv_bfloat16* srcs[4] = { Ah + go, Al + go, Wh + go, Wl + go };
#pragma unroll
        for (int arr = 0; arr < 4; arr++) {
#pragma unroll
            for (int i = 0; i < 2; i++) {
                const int row = lrow + i * 64;
                cpa16(base + arr * GTILE + row * GSTR + lcol * 16,
                      srcs[arr] + (size_t)row * K + lcol * 8);
            }
        }
        cpa_commit();
    };

    issue_chunk(0, 0); issue_chunk(1, 1); issue_chunk(2, 2);

    for (int c = 0; c < NCH; c++) {
        cpa_wait<2>();            // group c complete (c+1, c+2 may be pending)
        __syncthreads();          // data visible; all warps done with stage (c-1)%4
        if (c + 3 < NCH) issue_chunk(c + 3, (c + 3) & 3); else cpa_commit();

        const uint32_t bufb = sb + (c & 3) * GSTAGE;
#pragma unroll
        for (int ks = 0; ks < 2; ks++) {
            uint32_t a_h[4][4], a_l[4][4];
#pragma unroll
            for (int mt = 0; mt < 4; mt++) {
                const uint32_t ra = bufb +
                    (wm * 64 + mt * 16 + (lane & 15)) * GSTR +
                    ks * 32 + (lane >> 4) * 16;
                ldsm4(a_h[mt], ra);
                ldsm4(a_l[mt], ra + GTILE);
            }
#pragma unroll
            for (int nt2 = 0; nt2 < 2; nt2++) {
                const uint32_t rb = bufb + 2 * GTILE +
                    (wn * 32 + nt2 * 16 + (lane & 7) + ((lane >> 4) & 1) * 8) * GSTR +
                    ks * 32 + ((lane >> 3) & 1) * 16;
                uint32_t bh[4], bl[4];
                ldsm4(bh, rb);
                ldsm4(bl, rb + GTILE);
#pragma unroll
                for (int mt = 0; mt < 4; mt++) {
                    mma16816(acc[mt][2 * nt2],     a_h[mt], bh[0], bh[1]);
                    mma16816(acc[mt][2 * nt2],     a_h[mt], bl[0], bl[1]);
                    mma16816(acc[mt][2 * nt2],     a_l[mt], bh[0], bh[1]);
                    mma16816(acc[mt][2 * nt2 + 1], a_h[mt], bh[2], bh[3]);
                    mma16816(acc[mt][2 * nt2 + 1], a_h[mt], bl[2], bl[3]);
                    mma16816(acc[mt][2 * nt2 + 1], a_l[mt], bh[2], bh[3]);
                }
            }
        }
    }

    // epilogue
    const long long cb = (long long)z * strideCb;
    const int g = lane >> 2, tq = (lane & 3) * 2;
#pragma unroll
    for (int mt = 0; mt < 4; mt++) {
#pragma unroll
        for (int nt = 0; nt < 4; nt++) {
            const int row0 = m0 + wm * 64 + mt * 16 + g;
            const int col  = n0 + wn * 32 + nt * 8 + tq;
            float sv0 = 1.f, sv1 = 1.f, bv0 = 0.f, bv1 = 0.f;
            if (svec) {
                sv0 = __ldg(svec + (size_t)z * sStride + col);
                sv1 = __ldg(svec + (size_t)z * sStride + col + 1);
            }
            if (bias) { bv0 = __ldg(bias + col); bv1 = __ldg(bias + col + 1); }
            const float v0 = acc[mt][nt][0] * sv0 + bv0;
            const float v1 = acc[mt][nt][1] * sv1 + bv1;
            const float v2 = acc[mt][nt][2] * sv0 + bv0;
            const float v3 = acc[mt][nt][3] * sv1 + bv1;
            const size_t i0 = (size_t)(cb + (long long)row0 * ldc + col);
            const size_t i1 = i0 + (size_t)8 * ldc;
            if (Cf) {
                *(float2*)(Cf + i0) = make_float2(v0, v1);
                *(float2*)(Cf + i1) = make_float2(v2, v3);
            } else {
                uint32_t h, l;
                pack_hilo(v0, v1, h, l);
                *(uint32_t*)(Chi + i0) = h; *(uint32_t*)(Clo + i0) = l;
                pack_hilo(v2, v3, h, l);
                *(uint32_t*)(Chi + i1) = h; *(uint32_t*)(Clo + i1) = l;
            }
        }
    }
}

// ---------------------------------------------------------------------------
// Flash attention on mma.sync, 3-term. Block = (q-tile 128, head-batch n),
// 8 warps x 16 q-rows. KV blocks of 64 rows, 3-stage cp.async pipeline,
// one __syncthreads per iteration. P stays in registers.
// ---------------------------------------------------------------------------
namespace {
constexpr int KSTR  = 144;                  // 64 bf16 data + 16B pad
constexpr int QTILE = 128 * KSTR;           // 18432
constexpr int KTILE = 64 * KSTR;            // 9216
constexpr int KSTAGE = 4 * KTILE;           // Kh,Kl,Vh,Vl = 36864
constexpr int ATTN_SMEM = 2 * QTILE + 3 * KSTAGE;  // 147456
constexpr int NKB = 16;                     // 1024 / 64
constexpr float SC = 0.125f * 1.44269504f;  // hd^-0.5 * log2(e)
}

__global__ __launch_bounds__(256) void attn_mma_kernel(
    const __nv_bfloat16* __restrict__ qh_, const __nv_bfloat16* __restrict__ ql_,
    const __nv_bfloat16* __restrict__ kvh_, const __nv_bfloat16* __restrict__ kvl_,
    __nv_bfloat16* __restrict__ cxh, __nv_bfloat16* __restrict__ cxl)
{
    extern __shared__ char smraw[];
    const uint32_t sb = smem_u32(smraw);
    const uint32_t QH = 0, QL = QTILE, KVB = 2 * QTILE;

    const int tid = threadIdx.x, lane = tid & 31, wid = tid >> 5;
    const int n = blockIdx.y, b = n >> 4, j = n & 15;
    const int q0 = blockIdx.x * 128;

    // ---- issue Q load (1 group) ----
    {
        const __nv_bfloat16* s0 = qh_ + ((size_t)(b * TQ + q0)) * H + j * 64;
        const __nv_bfloat16* s1 = ql_ + ((size_t)(b * TQ + q0)) * H + j * 64;
#pragma unroll
        for (int i = 0; i < 4; i++) {
            const int id = tid + i * 256;
            const int row = id >> 3, cc = id & 7;
            cpa16(sb + QH + row * KSTR + cc * 16, s0 + (size_t)row * H + cc * 8);
            cpa16(sb + QL + row * KSTR + cc * 16, s1 + (size_t)row * H + cc * 8);
        }
        cpa_commit();
    }

    // ---- issue KV stages 0,1 ----
    const size_t kvcol = (size_t)j * 128;
    auto issue_kv = [&](int kb, int st) {
        const uint32_t base = sb + KVB + st * KSTAGE;
        const size_t rbase = (size_t)(b * TK + kb * 64);
#pragma unroll
        for (int i = 0; i < 2; i++) {
            const int id = tid + i * 256;
            const int row = id >> 3, cc = id & 7;
            const size_t gsrc = (rbase + row) * 2048 + kvcol + cc * 8;
            const uint32_t sof = base + row * KSTR + cc * 16;
            cpa16(sof,             kvh_ + gsrc);        // Kh
            cpa16(sof + KTILE,     kvl_ + gsrc);        // Kl
            cpa16(sof + 2 * KTILE, kvh_ + gsrc + 64);   // Vh
            cpa16(sof + 3 * KTILE, kvl_ + gsrc + 64);   // Vl
        }
        cpa_commit();
    };
    issue_kv(0, 0);
    issue_kv(1, 1);

    // ---- Q fragments to registers ----
    cpa_wait<2>();                // Q group done
    __syncthreads();
    uint32_t qfh[4][4], qfl[4][4];
#pragma unroll
    for (int kt = 0; kt < 4; kt++) {
        const uint32_t ra = sb + QH + (wid * 16 + (lane & 15)) * KSTR +
                            kt * 32 + (lane >> 4) * 16;
        ldsm4(qfh[kt], ra);
        ldsm4(qfl[kt], ra + QTILE);
    }

    float O[8][4];
#pragma unroll
    for (int d = 0; d < 8; d++)
#pragma unroll
        for (int e = 0; e < 4; e++) O[d][e] = 0.f;
    float mrow0 = -1e30f, mrow1 = -1e30f, lrow0 = 0.f, lrow1 = 0.f;

    for (int kb = 0; kb < NKB; kb++) {
        cpa_wait<1>();            // KV group kb complete
        __syncthreads();          // all warps done with stage (kb-1)%3
        if (kb + 2 < NKB) issue_kv(kb + 2, (kb + 2) % 3); else cpa_commit();

        const uint32_t stg = sb + KVB + (kb % 3) * KSTAGE;

        // ---- S = Q K^T (3-term): 8 n8-tiles ----
        float S[8][4];
#pragma unroll
        for (int t = 0; t < 8; t++)
#pragma unroll
            for (int e = 0; e < 4; e++) S[t][e] = 0.f;

#pragma unroll
        for (int nt2 = 0; nt2 < 4; nt2++) {
#pragma unroll
            for (int dt = 0; dt < 4; dt++) {
                const uint32_t rb = stg +
                    (nt2 * 16 + (lane & 7) + ((lane >> 4) & 1) * 8) * KSTR +
                    dt * 32 + ((lane >> 3) & 1) * 16;
                uint32_t bh[4], bl[4];
                ldsm4(bh, rb);
                ldsm4(bl, rb + KTILE);
                mma16816(S[2 * nt2],     qfh[dt], bh[0], bh[1]);
                mma16816(S[2 * nt2],     qfh[dt], bl[0], bl[1]);
                mma16816(S[2 * nt2],     qfl[dt], bh[0], bh[1]);
                mma16816(S[2 * nt2 + 1], qfh[dt], bh[2], bh[3]);
                mma16816(S[2 * nt2 + 1], qfh[dt], bl[2], bl[3]);
                mma16816(S[2 * nt2 + 1], qfl[dt], bh[2], bh[3]);
            }
        }

        // ---- online softmax (exp2 domain) ----
        float mx0 = -1e30f, mx1 = -1e30f;
#pragma unroll
        for (int t = 0; t < 8; t++) {
            S[t][0] *= SC; S[t][1] *= SC; S[t][2] *= SC; S[t][3] *= SC;
            mx0 = fmaxf(mx0, fmaxf(S[t][0], S[t][1]));
            mx1 = fmaxf(mx1, fmaxf(S[t][2], S[t][3]));
        }
        mx0 = fmaxf(mx0, __shfl_xor_sync(0xffffffffu, mx0, 1));
        mx0 = fmaxf(mx0, __shfl_xor_sync(0xffffffffu, mx0, 2));
        mx1 = fmaxf(mx1, __shfl_xor_sync(0xffffffffu, mx1, 1));
        mx1 = fmaxf(mx1, __shfl_xor_sync(0xffffffffu, mx1, 2));
        const float mn0 = fmaxf(mrow0, mx0), mn1 = fmaxf(mrow1, mx1);
        const float c0 = ex2(mrow0 - mn0), c1 = ex2(mrow1 - mn1);
        mrow0 = mn0; mrow1 = mn1;

        float sum0 = 0.f, sum1 = 0.f;
#pragma unroll
        for (int t = 0; t < 8; t++) {
            S[t][0] = ex2(S[t][0] - mn0); S[t][1] = ex2(S[t][1] - mn0);
            S[t][2] = ex2(S[t][2] - mn1); S[t][3] = ex2(S[t][3] - mn1);
            sum0 += S[t][0] + S[t][1];
            sum1 += S[t][2] + S[t][3];
        }
        sum0 += __shfl_xor_sync(0xffffffffu, sum0, 1);
        sum0 += __shfl_xor_sync(0xffffffffu, sum0, 2);
        sum1 += __shfl_xor_sync(0xffffffffu, sum1, 1);
        sum1 += __shfl_xor_sync(0xffffffffu, sum1, 2);
        lrow0 = lrow0 * c0 + sum0;
        lrow1 = lrow1 * c1 + sum1;
#pragma unroll
        for (int d = 0; d < 8; d++) {
            O[d][0] *= c0; O[d][1] *= c0; O[d][2] *= c1; O[d][3] *= c1;
        }

        // ---- P -> bf16 A-fragments (registers) ----
        uint32_t ph[4][4], pl[4][4];
#pragma unroll
        for (int kk = 0; kk < 4; kk++) {
            pack_hilo(S[2 * kk][0],     S[2 * kk][1],     ph[kk][0], pl[kk][0]);
            pack_hilo(S[2 * kk][2],     S[2 * kk][3],     ph[kk][1], pl[kk][1]);
            pack_hilo(S[2 * kk + 1][0], S[2 * kk + 1][1], ph[kk][2], pl[kk][2]);
            pack_hilo(S[2 * kk + 1][2], S[2 * kk + 1][3], ph[kk][3], pl[kk][3]);
        }

        // ---- O += P V (3-term) ----
#pragma unroll
        for (int kk = 0; kk < 4; kk++) {
#pragma unroll
            for (int dt2 = 0; dt2 < 4; dt2++) {
                const uint32_t rv = stg + 2 * KTILE +
                    (kk * 16 + (lane & 15)) * KSTR +
                    dt2 * 32 + (lane >> 4) * 16;
                uint32_t vh[4], vl[4];
                ldsm4t(vh, rv);
                ldsm4t(vl, rv + KTILE);
                mma16816(O[2 * dt2],     ph[kk], vh[0], vh[1]);
                mma16816(O[2 * dt2],     pl[kk], vh[0], vh[1]);
                mma16816(O[2 * dt2],     ph[kk], vl[0], vl[1]);
                mma16816(O[2 * dt2 + 1], ph[kk], vh[2], vh[3]);
                mma16816(O[2 * dt2 + 1], pl[kk], vh[2], vh[3]);
                mma16816(O[2 * dt2 + 1], ph[kk], vl[2], vl[3]);
            }
        }
    }

    // ---- epilogue ----
    const float i0 = 1.f / lrow0, i1 = 1.f / lrow1;
    const int g = lane >> 2, tq = (lane & 3) * 2;
    const int t0 = q0 + wid * 16 + g;
#pragma unroll
    for (int d = 0; d < 8; d++) {
        const int hcol = j * 64 + d * 8 + tq;
        const size_t idx0 = ((size_t)t0 * B + b) * H + hcol;
        const size_t idx1 = ((size_t)(t0 + 8) * B + b) * H + hcol;
        uint32_t h, l;
        pack_hilo(O[d][0] * i0, O[d][1] * i0, h, l);
        *(uint32_t*)(cxh + idx0) = h; *(uint32_t*)(cxl + idx0) = l;
        pack_hilo(O[d][2] * i1, O[d][3] * i1, h, l);
        *(uint32_t*)(cxh + idx1) = h; *(uint32_t*)(cxl + idx1) = l;
    }
}

// ---------------------------------------------------------------------------
extern "C" void kernel_launch(void* const* d_in, const int* in_sizes, int n_in,
                              void* d_out, int out_size)
{
    const float* inputs_q  = (const float*)d_in[0];
    const float* inputs_kv = (const float*)d_in[1];
    const float* w_q  = (const float*)d_in[2];
    const float* b_q  = (const float*)d_in[3];
    const float* w_kv = (const float*)d_in[4];
    const float* b_kv = (const float*)d_in[5];
    const float* w_o  = (const float*)d_in[6];
    const float* b_o  = (const float*)d_in[7];
    const float* r_q  = (const float*)d_in[8];
    const float* s_q  = (const float*)d_in[9];
    const float* r_kv = (const float*)d_in[10];
    const float* s_kv = (const float*)d_in[11];
    float* out = (float*)d_out;

    void* p;
    cudaGetSymbolAddress(&p, g_aq_h);  __nv_bfloat16* aqh = (__nv_bfloat16*)p;
    cudaGetSymbolAddress(&p, g_aq_l);  __nv_bfloat16* aql = (__nv_bfloat16*)p;
    cudaGetSymbolAddress(&p, g_akv_h); __nv_bfloat16* akh = (__nv_bfloat16*)p;
    cudaGetSymbolAddress(&p, g_akv_l); __nv_bfloat16* akl = (__nv_bfloat16*)p;
    cudaGetSymbolAddress(&p, g_wq_h);  __nv_bfloat16* wqh = (__nv_bfloat16*)p;
    cudaGetSymbolAddress(&p, g_wq_l);  __nv_bfloat16* wql = (__nv_bfloat16*)p;
    cudaGetSymbolAddress(&p, g_wkv_h); __nv_bfloat16* wkh = (__nv_bfloat16*)p;
    cudaGetSymbolAddress(&p, g_wkv_l); __nv_bfloat16* wkl = (__nv_bfloat16*)p;
    cudaGetSymbolAddress(&p, g_wo_h);  __nv_bfloat16* woh = (__nv_bfloat16*)p;
    cudaGetSymbolAddress(&p, g_wo_l);  __nv_bfloat16* wol = (__nv_bfloat16*)p;
    cudaGetSymbolAddress(&p, g_qh);    __nv_bfloat16* qh  = (__nv_bfloat16*)p;
    cudaGetSymbolAddress(&p, g_ql);    __nv_bfloat16* ql  = (__nv_bfloat16*)p;
    cudaGetSymbolAddress(&p, g_kvh);   __nv_bfloat16* kvh = (__nv_bfloat16*)p;
    cudaGetSymbolAddress(&p, g_kvl);   __nv_bfloat16* kvl = (__nv_bfloat16*)p;
    cudaGetSymbolAddress(&p, g_cxh);   __nv_bfloat16* cxh = (__nv_bfloat16*)p;
    cudaGetSymbolAddress(&p, g_cxl);   __nv_bfloat16* cxl = (__nv_bfloat16*)p;

    cudaFuncSetAttribute(gemm_mma_kernel, cudaFuncAttributeMaxDynamicSharedMemorySize, GEMM_SMEM);
    cudaFuncSetAttribute(attn_mma_kernel, cudaFuncAttributeMaxDynamicSharedMemorySize, ATTN_SMEM);

    const int act4 = TQ * B * H / 4;
    split_act_kernel<<<(act4 + 255) / 256, 256>>>(inputs_q,  r_q,  aqh, aql, TQ);
    split_act_kernel<<<(act4 + 255) / 256, 256>>>(inputs_kv, r_kv, akh, akl, TK);
    split_weights_kernel<<<(H * H + 255) / 256, 256>>>(   // 1M f4 elements total
        w_q, w_kv, w_o, wqh, wql, wkh, wkl, woh, wol);

    // q projection -> bf16 hi/lo q [b][t][H]
    gemm_mma_kernel<<<dim3(8, 8, 8), 256, GEMM_SMEM>>>(
        aqh, aql, wqh, wql, TQ, nullptr, qh, ql,
        H, (long long)TQ * H, s_q, H, b_q);

    // kv projection -> bf16 hi/lo kv [b][t][2H]
    gemm_mma_kernel<<<dim3(16, 8, 8), 256, GEMM_SMEM>>>(
        akh, akl, wkh, wkl, TK, nullptr, kvh, kvl,
        2 * H, (long long)TK * 2 * H, s_kv, 2 * H, b_kv);

    // attention -> ctx bf16 hi/lo [t][b][H]
    attn_mma_kernel<<<dim3(8, 128), 256, ATTN_SMEM>>>(qh, ql, kvh, kvl, cxh, cxl);

    // output projection -> fp32 out
    gemm_mma_kernel<<<dim3(8, 64, 1), 256, GEMM_SMEM>>>(
        cxh, cxl, woh, wol, TQ * B, out, nullptr, nullptr,
        H, 0LL, nullptr, 0, b_o);
}

// round 5
// speedup vs baseline: 1.0787x; 1.0787x over previous
#include <cuda_runtime.h>
#include <cuda_bf16.h>
#include <cstdint>

// ---------------------------------------------------------------------------
// BEEncdecMultiheadAttn: Tq=Tk=1024, B=8, H=1024, heads=16, hd=64
// Round 5: GEMM 2 CTAs/SM (80KB smem, <=128 regs); attention q-tile 256
// (2 strips/warp, shared K/V fragments), 3-stage KV pipeline; softmax scale
// folded into q projection.
// ---------------------------------------------------------------------------

namespace {
constexpr int TQ = 1024, TK = 1024, B = 8, H = 1024, K = 1024;
}

__device__ __nv_bfloat16 g_aq_h [B * TQ * H], g_aq_l [B * TQ * H];
__device__ __nv_bfloat16 g_akv_h[B * TK * H], g_akv_l[B * TK * H];
__device__ __nv_bfloat16 g_wq_h [H * H],      g_wq_l [H * H];
__device__ __nv_bfloat16 g_wkv_h[2 * H * H],  g_wkv_l[2 * H * H];
__device__ __nv_bfloat16 g_wo_h [H * H],      g_wo_l [H * H];
__device__ __nv_bfloat16 g_qh [B * TQ * H],      g_ql [B * TQ * H];       // [b][t][H]
__device__ __nv_bfloat16 g_kvh[B * TK * 2 * H],  g_kvl[B * TK * 2 * H];   // [b][t][2H]
__device__ __nv_bfloat16 g_cxh[TQ * B * H],      g_cxl[TQ * B * H];       // [t][b][H]

// ---------------------------------------------------------------------------
// helpers (sm_80+ baseline PTX only)
// ---------------------------------------------------------------------------
__device__ __forceinline__ uint32_t smem_u32(const void* p) {
    uint32_t a;
    asm("{ .reg .u64 t; cvta.to.shared.u64 t, %1; cvt.u32.u64 %0, t; }" : "=r"(a) : "l"(p));
    return a;
}
__device__ __forceinline__ void cpa16(uint32_t dst, const void* src) {
    asm volatile("cp.async.cg.shared.global [%0], [%1], 16;" :: "r"(dst), "l"(src));
}
__device__ __forceinline__ void cpa_commit() { asm volatile("cp.async.commit_group;" ::: "memory"); }
template <int N>
__device__ __forceinline__ void cpa_wait() { asm volatile("cp.async.wait_group %0;" :: "n"(N) : "memory"); }

__device__ __forceinline__ void ldsm4(uint32_t r[4], uint32_t addr) {
    asm volatile("ldmatrix.sync.aligned.m8n8.x4.shared.b16 {%0,%1,%2,%3}, [%4];"
                 : "=r"(r[0]), "=r"(r[1]), "=r"(r[2]), "=r"(r[3]) : "r"(addr));
}
__device__ __forceinline__ void ldsm4t(uint32_t r[4], uint32_t addr) {
    asm volatile("ldmatrix.sync.aligned.m8n8.x4.trans.shared.b16 {%0,%1,%2,%3}, [%4];"
                 : "=r"(r[0]), "=r"(r[1]), "=r"(r[2]), "=r"(r[3]) : "r"(addr));
}
__device__ __forceinline__ void mma16816(float c[4], const uint32_t a[4], uint32_t b0, uint32_t b1) {
    asm volatile(
        "mma.sync.aligned.m16n8k16.row.col.f32.bf16.bf16.f32 "
        "{%0,%1,%2,%3}, {%4,%5,%6,%7}, {%8,%9}, {%0,%1,%2,%3};"
        : "+f"(c[0]), "+f"(c[1]), "+f"(c[2]), "+f"(c[3])
        : "r"(a[0]), "r"(a[1]), "r"(a[2]), "r"(a[3]), "r"(b0), "r"(b1));
}
__device__ __forceinline__ float ex2(float x) {
    float y; asm("ex2.approx.ftz.f32 %0, %1;" : "=f"(y) : "f"(x)); return y;
}
__device__ __forceinline__ uint32_t pack_bf2(__nv_bfloat16 x, __nv_bfloat16 y) {
    __nv_bfloat162 t = __halves2bfloat162(x, y);
    return *reinterpret_cast<uint32_t*>(&t);
}
__device__ __forceinline__ void pack_hilo(float a, float b, uint32_t& h, uint32_t& l) {
    __nv_bfloat16 ha = __float2bfloat16_rn(a), hb = __float2bfloat16_rn(b);
    __nv_bfloat16 la = __float2bfloat16_rn(a - __bfloat162float(ha));
    __nv_bfloat16 lb = __float2bfloat16_rn(b - __bfloat162float(hb));
    h = pack_bf2(ha, hb);
    l = pack_bf2(la, lb);
}
__device__ __forceinline__ void split2(float x, __nv_bfloat16& h, __nv_bfloat16& l) {
    h = __float2bfloat16_rn(x);
    l = __float2bfloat16_rn(x - __bfloat162float(h));
}

// ---------------------------------------------------------------------------
// split kernels
// ---------------------------------------------------------------------------
__global__ __launch_bounds__(256) void split_act_kernel(
    const float* __restrict__ x, const float* __restrict__ r,
    __nv_bfloat16* __restrict__ hi, __nv_bfloat16* __restrict__ lo, int T)
{
    const int i = blockIdx.x * blockDim.x + threadIdx.x;
    if (i >= T * B * H / 4) return;
    const int e = i * 4, h = e % H, tb = e / H, b = tb % B, t = tb / B;
    float4 xv = ((const float4*)x)[i];
    float4 rv = *(const float4*)(r + b * H + h);
    xv.x *= rv.x; xv.y *= rv.y; xv.z *= rv.z; xv.w *= rv.w;
    __nv_bfloat16 h0, h1, h2, h3, l0, l1, l2, l3;
    split2(xv.x, h0, l0); split2(xv.y, h1, l1); split2(xv.z, h2, l2); split2(xv.w, h3, l3);
    const size_t o = ((size_t)b * T + t) * H + h;
    *(__nv_bfloat162*)(hi + o)     = __halves2bfloat162(h0, h1);
    *(__nv_bfloat162*)(hi + o + 2) = __halves2bfloat162(h2, h3);
    *(__nv_bfloat162*)(lo + o)     = __halves2bfloat162(l0, l1);
    *(__nv_bfloat162*)(lo + o + 2) = __halves2bfloat162(l2, l3);
}

__global__ __launch_bounds__(256) void split_weights_kernel(
    const float* __restrict__ wq, const float* __restrict__ wkv, const float* __restrict__ wo,
    __nv_bfloat16* __restrict__ qh, __nv_bfloat16* __restrict__ ql,
    __nv_bfloat16* __restrict__ kh, __nv_bfloat16* __restrict__ kl,
    __nv_bfloat16* __restrict__ oh, __nv_bfloat16* __restrict__ ol)
{
    const int i = blockIdx.x * blockDim.x + threadIdx.x;
    constexpr int NQ = H * H / 4, NKV = 2 * H * H / 4;
    const float* src; __nv_bfloat16 *hi, *lo; int j;
    if (i < NQ)            { src = wq;  hi = qh; lo = ql; j = i; }
    else if (i < NQ + NKV) { src = wkv; hi = kh; lo = kl; j = i - NQ; }
    else                   { src = wo;  hi = oh; lo = ol; j = i - NQ - NKV; }
    float4 xv = ((const float4*)src)[j];
    __nv_bfloat16 h0, h1, h2, h3, l0, l1, l2, l3;
    split2(xv.x, h0, l0); split2(xv.y, h1, l1); split2(xv.z, h2, l2); split2(xv.w, h3, l3);
    const size_t o = (size_t)j * 4;
    *(__nv_bfloat162*)(hi + o)     = __halves2bfloat162(h0, h1);
    *(__nv_bfloat162*)(hi + o + 2) = __halves2bfloat162(h2, h3);
    *(__nv_bfloat162*)(lo + o)     = __halves2bfloat162(l0, l1);
    *(__nv_bfloat162*)(lo + o + 2) = __halves2bfloat162(l2, l3);
}

// ---------------------------------------------------------------------------
// GEMM: C = (Ah+Al)(Wh+Wl)^T (3-term), epi: C = (C*s[n]+bias[n])*outScale.
// 128x128 tile, K-chunk 32, 2-stage cp.async double buffer, 80KB smem,
// 2 CTAs/SM (regs capped at 128 via launch bounds).
// ---------------------------------------------------------------------------
namespace {
constexpr int GSTR = 80;
constexpr int GTILE = 128 * GSTR;        // 10240
constexpr int GSTAGE = 4 * GTILE;        // 40960
constexpr int GEMM_SMEM = 2 * GSTAGE;    // 81920
constexpr int NCH = 32;
}

__global__ __launch_bounds__(256, 2) void gemm_mma_kernel(
    const __nv_bfloat16* __restrict__ ah, const __nv_bfloat16* __restrict__ al,
    const __nv_bfloat16* __restrict__ wh, const __nv_bfloat16* __restrict__ wl,
    int Mb,
    float* __restrict__ Cf, __nv_bfloat16* __restrict__ Chi, __nv_bfloat16* __restrict__ Clo,
    int ldc, long long strideCb,
    const float* __restrict__ svec, int sStride, const float* __restrict__ bias,
    float outScale)
{
    extern __shared__ char smraw[];
    const uint32_t sb = smem_u32(smraw);

    const int tid = threadIdx.x, lane = tid & 31, wid = tid >> 5;
    const int wm = wid & 1, wn = wid >> 1;
    const int n0 = blockIdx.x * 128, m0 = blockIdx.y * 128, z = blockIdx.z;

    const __nv_bfloat16* Ah = ah + (size_t)z * Mb * K + (size_t)m0 * K;
    const __nv_bfloat16* Al = al + (size_t)z * Mb * K + (size_t)m0 * K;
    const __nv_bfloat16* Wh = wh + (size_t)n0 * K;
    const __nv_bfloat16* Wl = wl + (size_t)n0 * K;

    float acc[4][4][4];
#pragma unroll
    for (int a = 0; a < 4; a++)
#pragma unroll
        for (int b = 0; b < 4; b++)
#pragma unroll
            for (int c = 0; c < 4; c++) acc[a][b][c] = 0.f;

    const int lrow = tid >> 2, lcol = tid & 3;
    auto issue_chunk = [&](int c, int st) {
        const uint32_t base = sb + st * GSTAGE;
        const size_t go = (size_t)c * 32;
        const __nv_bfloat16* srcs[4] = { Ah + go, Al + go, Wh + go, Wl + go };
#pragma unroll
        for (int arr = 0; arr < 4; arr++) {
#pragma unroll
            for (int i = 0; i < 2; i++) {
                const int row = lrow + i * 64;
                cpa16(base + arr * GTILE + row * GSTR + lcol * 16,
                      srcs[arr] + (size_t)row * K + lcol * 8);
            }
        }
        cpa_commit();
    };

    issue_chunk(0, 0);

    for (int c = 0; c < NCH; c++) {
        cpa_wait<0>();
        __syncthreads();
        if (c + 1 < NCH) issue_chunk(c + 1, (c + 1) & 1);

        const uint32_t bufb = sb + (c & 1) * GSTAGE;
#pragma unroll
        for (int ks = 0; ks < 2; ks++) {
            uint32_t a_h[4][4], a_l[4][4];
#pragma unroll
            for (int mt = 0; mt < 4; mt++) {
                const uint32_t ra = bufb +
                    (wm * 64 + mt * 16 + (lane & 15)) * GSTR +
                    ks * 32 + (lane >> 4) * 16;
                ldsm4(a_h[mt], ra);
                ldsm4(a_l[mt], ra + GTILE);
            }
#pragma unroll
            for (int nt2 = 0; nt2 < 2; nt2++) {
                const uint32_t rb = bufb + 2 * GTILE +
                    (wn * 32 + nt2 * 16 + (lane & 7) + ((lane >> 4) & 1) * 8) * GSTR +
                    ks * 32 + ((lane >> 3) & 1) * 16;
                uint32_t bh[4], bl[4];
                ldsm4(bh, rb);
                ldsm4(bl, rb + GTILE);
#pragma unroll
                for (int mt = 0; mt < 4; mt++) {
                    mma16816(acc[mt][2 * nt2],     a_h[mt], bh[0], bh[1]);
                    mma16816(acc[mt][2 * nt2],     a_h[mt], bl[0], bl[1]);
                    mma16816(acc[mt][2 * nt2],     a_l[mt], bh[0], bh[1]);
                    mma16816(acc[mt][2 * nt2 + 1], a_h[mt], bh[2], bh[3]);
                    mma16816(acc[mt][2 * nt2 + 1], a_h[mt], bl[2], bl[3]);
                    mma16816(acc[mt][2 * nt2 + 1], a_l[mt], bh[2], bh[3]);
                }
            }
        }
        __syncthreads();
    }

    // epilogue
    const long long cb = (long long)z * strideCb;
    const int g = lane >> 2, tq = (lane & 3) * 2;
#pragma unroll
    for (int mt = 0; mt < 4; mt++) {
#pragma unroll
        for (int nt = 0; nt < 4; nt++) {
            const int row0 = m0 + wm * 64 + mt * 16 + g;
            const int col  = n0 + wn * 32 + nt * 8 + tq;
            float sv0 = 1.f, sv1 = 1.f, bv0 = 0.f, bv1 = 0.f;
            if (svec) {
                sv0 = __ldg(svec + (size_t)z * sStride + col);
                sv1 = __ldg(svec + (size_t)z * sStride + col + 1);
            }
            if (bias) { bv0 = __ldg(bias + col); bv1 = __ldg(bias + col + 1); }
            const float v0 = (acc[mt][nt][0] * sv0 + bv0) * outScale;
            const float v1 = (acc[mt][nt][1] * sv1 + bv1) * outScale;
            const float v2 = (acc[mt][nt][2] * sv0 + bv0) * outScale;
            const float v3 = (acc[mt][nt][3] * sv1 + bv1) * outScale;
            const size_t i0 = (size_t)(cb + (long long)row0 * ldc + col);
            const size_t i1 = i0 + (size_t)8 * ldc;
            if (Cf) {
                *(float2*)(Cf + i0) = make_float2(v0, v1);
                *(float2*)(Cf + i1) = make_float2(v2, v3);
            } else {
                uint32_t h, l;
                pack_hilo(v0, v1, h, l);
                *(uint32_t*)(Chi + i0) = h; *(uint32_t*)(Clo + i0) = l;
                pack_hilo(v2, v3, h, l);
                *(uint32_t*)(Chi + i1) = h; *(uint32_t*)(Clo + i1) = l;
            }
        }
    }
}

// ---------------------------------------------------------------------------
// Flash attention, q-tile 256 per CTA; 8 warps, each owning two 16-row
// strips (rows wid*16 and 128+wid*16). K/V fragments shared by both strips.
// KV blocks of 64 rows, 3-stage cp.async pipeline. Q pre-scaled by
// hd^-0.5*log2(e) in the q-projection epilogue, so softmax uses ex2 directly.
// ---------------------------------------------------------------------------
namespace {
constexpr int KSTR   = 144;
constexpr int QTILE  = 256 * KSTR;                 // hi or lo: 36864
constexpr int KTILE  = 64 * KSTR;                  // 9216
constexpr int KSTAGE = 4 * KTILE;                  // 36864
constexpr int ATTN_SMEM = 2 * QTILE + 3 * KSTAGE;  // 184320
constexpr int NKB = 16;
}

__global__ __launch_bounds__(256, 1) void attn_mma_kernel(
    const __nv_bfloat16* __restrict__ qh_, const __nv_bfloat16* __restrict__ ql_,
    const __nv_bfloat16* __restrict__ kvh_, const __nv_bfloat16* __restrict__ kvl_,
    __nv_bfloat16* __restrict__ cxh, __nv_bfloat16* __restrict__ cxl)
{
    extern __shared__ char smraw[];
    const uint32_t sb = smem_u32(smraw);
    const uint32_t QH = 0, QL = QTILE, KVB = 2 * QTILE;

    const int tid = threadIdx.x, lane = tid & 31, wid = tid >> 5;
    const int n = blockIdx.y, b = n >> 4, j = n & 15;
    const int q0 = blockIdx.x * 256;

    // ---- issue Q load (256 rows hi+lo, 1 group) ----
    {
        const __nv_bfloat16* s0 = qh_ + ((size_t)(b * TQ + q0)) * H + j * 64;
        const __nv_bfloat16* s1 = ql_ + ((size_t)(b * TQ + q0)) * H + j * 64;
#pragma unroll
        for (int i = 0; i < 8; i++) {
            const int id = tid + i * 256;
            const int row = id >> 3, cc = id & 7;
            cpa16(sb + QH + row * KSTR + cc * 16, s0 + (size_t)row * H + cc * 8);
            cpa16(sb + QL + row * KSTR + cc * 16, s1 + (size_t)row * H + cc * 8);
        }
        cpa_commit();
    }

    const size_t kvcol = (size_t)j * 128;
    auto issue_kv = [&](int kb, int st) {
        const uint32_t base = sb + KVB + st * KSTAGE;
        const size_t rbase = (size_t)(b * TK + kb * 64);
#pragma unroll
        for (int i = 0; i < 2; i++) {
            const int id = tid + i * 256;
            const int row = id >> 3, cc = id & 7;
            const size_t gsrc = (rbase + row) * 2048 + kvcol + cc * 8;
            const uint32_t sof = base + row * KSTR + cc * 16;
            cpa16(sof,             kvh_ + gsrc);
            cpa16(sof + KTILE,     kvl_ + gsrc);
            cpa16(sof + 2 * KTILE, kvh_ + gsrc + 64);
            cpa16(sof + 3 * KTILE, kvl_ + gsrc + 64);
        }
        cpa_commit();
    };
    issue_kv(0, 0);
    issue_kv(1, 1);

    // ---- Q fragments to registers (2 strips, hi+lo) ----
    cpa_wait<2>();
    __syncthreads();
    uint32_t qfh[2][4][4], qfl[2][4][4];
#pragma unroll
    for (int s = 0; s < 2; s++)
#pragma unroll
        for (int kt = 0; kt < 4; kt++) {
            const uint32_t ra = sb + QH +
                (s * 128 + wid * 16 + (lane & 15)) * KSTR +
                kt * 32 + (lane >> 4) * 16;
            ldsm4(qfh[s][kt], ra);
            ldsm4(qfl[s][kt], ra + QTILE);
        }

    float O[2][8][4];
#pragma unroll
    for (int s = 0; s < 2; s++)
#pragma unroll
        for (int d = 0; d < 8; d++)
#pragma unroll
            for (int e = 0; e < 4; e++) O[s][d][e] = 0.f;
    float mrow[2][2] = {{-1e30f, -1e30f}, {-1e30f, -1e30f}};
    float lrow[2][2] = {{0.f, 0.f}, {0.f, 0.f}};

    uint32_t ph[2][4][4], pl[2][4][4];

    for (int kb = 0; kb < NKB; kb++) {
        cpa_wait<1>();
        __syncthreads();
        if (kb + 2 < NKB) issue_kv(kb + 2, (kb + 2) % 3); else cpa_commit();

        const uint32_t stg = sb + KVB + (kb % 3) * KSTAGE;

        // ---- per strip: S = Q K^T, softmax, pack P ----
#pragma unroll
        for (int s = 0; s < 2; s++) {
            float S[8][4];
#pragma unroll
            for (int t = 0; t < 8; t++)
#pragma unroll
                for (int e = 0; e < 4; e++) S[t][e] = 0.f;

#pragma unroll
            for (int nt2 = 0; nt2 < 4; nt2++) {
#pragma unroll
                for (int dt = 0; dt < 4; dt++) {
                    const uint32_t rb = stg +
                        (nt2 * 16 + (lane & 7) + ((lane >> 4) & 1) * 8) * KSTR +
                        dt * 32 + ((lane >> 3) & 1) * 16;
                    uint32_t bh[4], bl[4];
                    ldsm4(bh, rb);
                    ldsm4(bl, rb + KTILE);
                    mma16816(S[2 * nt2],     qfh[s][dt], bh[0], bh[1]);
                    mma16816(S[2 * nt2],     qfh[s][dt], bl[0], bl[1]);
                    mma16816(S[2 * nt2],     qfl[s][dt], bh[0], bh[1]);
                    mma16816(S[2 * nt2 + 1], qfh[s][dt], bh[2], bh[3]);
                    mma16816(S[2 * nt2 + 1], qfh[s][dt], bl[2], bl[3]);
                    mma16816(S[2 * nt2 + 1], qfl[s][dt], bh[2], bh[3]);
                }
            }

            // online softmax; Q pre-scaled so S already in log2 units
            float mx0 = -1e30f, mx1 = -1e30f;
#pragma unroll
            for (int t = 0; t < 8; t++) {
                mx0 = fmaxf(mx0, fmaxf(S[t][0], S[t][1]));
                mx1 = fmaxf(mx1, fmaxf(S[t][2], S[t][3]));
            }
            mx0 = fmaxf(mx0, __shfl_xor_sync(0xffffffffu, mx0, 1));
            mx0 = fmaxf(mx0, __shfl_xor_sync(0xffffffffu, mx0, 2));
            mx1 = fmaxf(mx1, __shfl_xor_sync(0xffffffffu, mx1, 1));
            mx1 = fmaxf(mx1, __shfl_xor_sync(0xffffffffu, mx1, 2));
            const float mn0 = fmaxf(mrow[s][0], mx0), mn1 = fmaxf(mrow[s][1], mx1);
            const float c0 = ex2(mrow[s][0] - mn0), c1 = ex2(mrow[s][1] - mn1);
            mrow[s][0] = mn0; mrow[s][1] = mn1;

            float sum0 = 0.f, sum1 = 0.f;
#pragma unroll
            for (int t = 0; t < 8; t++) {
                S[t][0] = ex2(S[t][0] - mn0); S[t][1] = ex2(S[t][1] - mn0);
                S[t][2] = ex2(S[t][2] - mn1); S[t][3] = ex2(S[t][3] - mn1);
                sum0 += S[t][0] + S[t][1];
                sum1 += S[t][2] + S[t][3];
            }
            sum0 += __shfl_xor_sync(0xffffffffu, sum0, 1);
            sum0 += __shfl_xor_sync(0xffffffffu, sum0, 2);
            sum1 += __shfl_xor_sync(0xffffffffu, sum1, 1);
            sum1 += __shfl_xor_sync(0xffffffffu, sum1, 2);
            lrow[s][0] = lrow[s][0] * c0 + sum0;
            lrow[s][1] = lrow[s][1] * c1 + sum1;
#pragma unroll
            for (int d = 0; d < 8; d++) {
                O[s][d][0] *= c0; O[s][d][1] *= c0; O[s][d][2] *= c1; O[s][d][3] *= c1;
            }

#pragma unroll
            for (int kk = 0; kk < 4; kk++) {
                pack_hilo(S[2 * kk][0],     S[2 * kk][1],     ph[s][kk][0], pl[s][kk][0]);
                pack_hilo(S[2 * kk][2],     S[2 * kk][3],     ph[s][kk][1], pl[s][kk][1]);
                pack_hilo(S[2 * kk + 1][0], S[2 * kk + 1][1], ph[s][kk][2], pl[s][kk][2]);
                pack_hilo(S[2 * kk + 1][2], S[2 * kk + 1][3], ph[s][kk][3], pl[s][kk][3]);
            }
        }

        // ---- O += P V (3-term), V fragments shared by both strips ----
#pragma unroll
        for (int kk = 0; kk < 4; kk++) {
#pragma unroll
            for (int dt2 = 0; dt2 < 4; dt2++) {
                const uint32_t rv = stg + 2 * KTILE +
                    (kk * 16 + (lane & 15)) * KSTR +
                    dt2 * 32 + (lane >> 4) * 16;
                uint32_t vh[4], vl[4];
                ldsm4t(vh, rv);
                ldsm4t(vl, rv + KTILE);
#pragma unroll
                for (int s = 0; s < 2; s++) {
                    mma16816(O[s][2 * dt2],     ph[s][kk], vh[0], vh[1]);
                    mma16816(O[s][2 * dt2],     pl[s][kk], vh[0], vh[1]);
                    mma16816(O[s][2 * dt2],     ph[s][kk], vl[0], vl[1]);
                    mma16816(O[s][2 * dt2 + 1], ph[s][kk], vh[2], vh[3]);
                    mma16816(O[s][2 * dt2 + 1], pl[s][kk], vh[2], vh[3]);
                    mma16816(O[s][2 * dt2 + 1], ph[s][kk], vl[2], vl[3]);
                }
            }
        }
    }

    // ---- epilogue ----
    const int g = lane >> 2, tq = (lane & 3) * 2;
#pragma unroll
    for (int s = 0; s < 2; s++) {
        const float i0 = 1.f / lrow[s][0], i1 = 1.f / lrow[s][1];
        const int t0 = q0 + s * 128 + wid * 16 + g;
#pragma unroll
        for (int d = 0; d < 8; d++) {
            const int hcol = j * 64 + d * 8 + tq;
            const size_t idx0 = ((size_t)t0 * B + b) * H + hcol;
            const size_t idx1 = ((size_t)(t0 + 8) * B + b) * H + hcol;
            uint32_t h, l;
            pack_hilo(O[s][d][0] * i0, O[s][d][1] * i0, h, l);
            *(uint32_t*)(cxh + idx0) = h; *(uint32_t*)(cxl + idx0) = l;
            pack_hilo(O[s][d][2] * i1, O[s][d][3] * i1, h, l);
            *(uint32_t*)(cxh + idx1) = h; *(uint32_t*)(cxl + idx1) = l;
        }
    }
}

// ---------------------------------------------------------------------------
extern "C" void kernel_launch(void* const* d_in, const int* in_sizes, int n_in,
                              void* d_out, int out_size)
{
    const float* inputs_q  = (const float*)d_in[0];
    const float* inputs_kv = (const float*)d_in[1];
    const float* w_q  = (const float*)d_in[2];
    const float* b_q  = (const float*)d_in[3];
    const float* w_kv = (const float*)d_in[4];
    const float* b_kv = (const float*)d_in[5];
    const float* w_o  = (const float*)d_in[6];
    const float* b_o  = (const float*)d_in[7];
    const float* r_q  = (const float*)d_in[8];
    const float* s_q  = (const float*)d_in[9];
    const float* r_kv = (const float*)d_in[10];
    const float* s_kv = (const float*)d_in[11];
    float* out = (float*)d_out;

    void* p;
    cudaGetSymbolAddress(&p, g_aq_h);  __nv_bfloat16* aqh = (__nv_bfloat16*)p;
    cudaGetSymbolAddress(&p, g_aq_l);  __nv_bfloat16* aql = (__nv_bfloat16*)p;
    cudaGetSymbolAddress(&p, g_akv_h); __nv_bfloat16* akh = (__nv_bfloat16*)p;
    cudaGetSymbolAddress(&p, g_akv_l); __nv_bfloat16* akl = (__nv_bfloat16*)p;
    cudaGetSymbolAddress(&p, g_wq_h);  __nv_bfloat16* wqh = (__nv_bfloat16*)p;
    cudaGetSymbolAddress(&p, g_wq_l);  __nv_bfloat16* wql = (__nv_bfloat16*)p;
    cudaGetSymbolAddress(&p, g_wkv_h); __nv_bfloat16* wkh = (__nv_bfloat16*)p;
    cudaGetSymbolAddress(&p, g_wkv_l); __nv_bfloat16* wkl = (__nv_bfloat16*)p;
    cudaGetSymbolAddress(&p, g_wo_h);  __nv_bfloat16* woh = (__nv_bfloat16*)p;
    cudaGetSymbolAddress(&p, g_wo_l);  __nv_bfloat16* wol = (__nv_bfloat16*)p;
    cudaGetSymbolAddress(&p, g_qh);    __nv_bfloat16* qh  = (__nv_bfloat16*)p;
    cudaGetSymbolAddress(&p, g_ql);    __nv_bfloat16* ql  = (__nv_bfloat16*)p;
    cudaGetSymbolAddress(&p, g_kvh);   __nv_bfloat16* kvh = (__nv_bfloat16*)p;
    cudaGetSymbolAddress(&p, g_kvl);   __nv_bfloat16* kvl = (__nv_bfloat16*)p;
    cudaGetSymbolAddress(&p, g_cxh);   __nv_bfloat16* cxh = (__nv_bfloat16*)p;
    cudaGetSymbolAddress(&p, g_cxl);   __nv_bfloat16* cxl = (__nv_bfloat16*)p;

    cudaFuncSetAttribute(gemm_mma_kernel, cudaFuncAttributeMaxDynamicSharedMemorySize, GEMM_SMEM);
    cudaFuncSetAttribute(attn_mma_kernel, cudaFuncAttributeMaxDynamicSharedMemorySize, ATTN_SMEM);

    const float SCALE = 0.125f * 1.44269504f;   // hd^-0.5 * log2(e)

    const int act4 = TQ * B * H / 4;
    split_act_kernel<<<(act4 + 255) / 256, 256>>>(inputs_q,  r_q,  aqh, aql, TQ);
    split_act_kernel<<<(act4 + 255) / 256, 256>>>(inputs_kv, r_kv, akh, akl, TK);
    split_weights_kernel<<<(H * H + 255) / 256, 256>>>(
        w_q, w_kv, w_o, wqh, wql, wkh, wkl, woh, wol);

    // q projection -> bf16 hi/lo q [b][t][H], pre-scaled for softmax
    gemm_mma_kernel<<<dim3(8, 8, 8), 256, GEMM_SMEM>>>(
        aqh, aql, wqh, wql, TQ, nullptr, qh, ql,
        H, (long long)TQ * H, s_q, H, b_q, SCALE);

    // kv projection -> bf16 hi/lo kv [b][t][2H]
    gemm_mma_kernel<<<dim3(16, 8, 8), 256, GEMM_SMEM>>>(
        akh, akl, wkh, wkl, TK, nullptr, kvh, kvl,
        2 * H, (long long)TK * 2 * H, s_kv, 2 * H, b_kv, 1.0f);

    // attention -> ctx bf16 hi/lo [t][b][H]
    attn_mma_kernel<<<dim3(4, 128), 256, ATTN_SMEM>>>(qh, ql, kvh, kvl, cxh, cxl);

    // output projection -> fp32 out
    gemm_mma_kernel<<<dim3(8, 64, 1), 256, GEMM_SMEM>>>(
        cxh, cxl, woh, wol, TQ * B, out, nullptr, nullptr,
        H, 0LL, nullptr, 0, b_o, 1.0f);
}

// round 6
// speedup vs baseline: 1.7908x; 1.6602x over previous
#include <cuda_runtime.h>
#include <cuda_fp16.h>
#include <cstdint>

// ---------------------------------------------------------------------------
// BEEncdecMultiheadAttn: Tq=Tk=1024, B=8, H=1024, heads=16, hd=64
// Round 6: fp16 single-pass projections (eps 2^-12), fp16 3-term attention
// (eps 2^-24). 4-stage cp.async GEMM pipeline, 2 CTAs/SM.
// ---------------------------------------------------------------------------

namespace {
constexpr int TQ = 1024, TK = 1024, B = 8, H = 1024, K = 1024;
}

// scratch (device globals: allocation-free)
__device__ __half g_aq [B * TQ * H];        // activations q  [b][t][H]
__device__ __half g_akv[B * TK * H];        // activations kv [b][t][H]
__device__ __half g_wq [H * H];
__device__ __half g_wkv[2 * H * H];
__device__ __half g_wo [H * H];
__device__ __half g_qh [B * TQ * H],     g_ql [B * TQ * H];      // q hi/lo   [b][t][H]
__device__ __half g_kvh[B * TK * 2 * H], g_kvl[B * TK * 2 * H];  // kv hi/lo  [b][t][2H]
__device__ __half g_cx [TQ * B * H];                              // ctx single [t][b][H]

// ---------------------------------------------------------------------------
// helpers (sm_80+ baseline PTX only)
// ---------------------------------------------------------------------------
__device__ __forceinline__ uint32_t smem_u32(const void* p) {
    uint32_t a;
    asm("{ .reg .u64 t; cvta.to.shared.u64 t, %1; cvt.u32.u64 %0, t; }" : "=r"(a) : "l"(p));
    return a;
}
__device__ __forceinline__ void cpa16(uint32_t dst, const void* src) {
    asm volatile("cp.async.cg.shared.global [%0], [%1], 16;" :: "r"(dst), "l"(src));
}
__device__ __forceinline__ void cpa_commit() { asm volatile("cp.async.commit_group;" ::: "memory"); }
template <int N>
__device__ __forceinline__ void cpa_wait() { asm volatile("cp.async.wait_group %0;" :: "n"(N) : "memory"); }

__device__ __forceinline__ void ldsm4(uint32_t r[4], uint32_t addr) {
    asm volatile("ldmatrix.sync.aligned.m8n8.x4.shared.b16 {%0,%1,%2,%3}, [%4];"
                 : "=r"(r[0]), "=r"(r[1]), "=r"(r[2]), "=r"(r[3]) : "r"(addr));
}
__device__ __forceinline__ void ldsm4t(uint32_t r[4], uint32_t addr) {
    asm volatile("ldmatrix.sync.aligned.m8n8.x4.trans.shared.b16 {%0,%1,%2,%3}, [%4];"
                 : "=r"(r[0]), "=r"(r[1]), "=r"(r[2]), "=r"(r[3]) : "r"(addr));
}
__device__ __forceinline__ void mma16816h(float c[4], const uint32_t a[4], uint32_t b0, uint32_t b1) {
    asm volatile(
        "mma.sync.aligned.m16n8k16.row.col.f32.f16.f16.f32 "
        "{%0,%1,%2,%3}, {%4,%5,%6,%7}, {%8,%9}, {%0,%1,%2,%3};"
        : "+f"(c[0]), "+f"(c[1]), "+f"(c[2]), "+f"(c[3])
        : "r"(a[0]), "r"(a[1]), "r"(a[2]), "r"(a[3]), "r"(b0), "r"(b1));
}
__device__ __forceinline__ float ex2(float x) {
    float y; asm("ex2.approx.ftz.f32 %0, %1;" : "=f"(y) : "f"(x)); return y;
}
__device__ __forceinline__ uint32_t pack_h2(__half x, __half y) {
    __half2 t = __halves2half2(x, y);
    return *reinterpret_cast<uint32_t*>(&t);
}
__device__ __forceinline__ void pack_hilo_h(float a, float b, uint32_t& h, uint32_t& l) {
    __half ha = __float2half_rn(a), hb = __float2half_rn(b);
    __half la = __float2half_rn(a - __half2float(ha));
    __half lb = __float2half_rn(b - __half2float(hb));
    h = pack_h2(ha, hb);
    l = pack_h2(la, lb);
}

// ---------------------------------------------------------------------------
// prep kernels: fp32 -> single fp16 (with r-scale for activations)
// ---------------------------------------------------------------------------
__global__ __launch_bounds__(256) void prep_act_kernel(
    const float* __restrict__ x, const float* __restrict__ r,
    __half* __restrict__ dst, int T)
{
    const int i = blockIdx.x * blockDim.x + threadIdx.x;
    if (i >= T * B * H / 4) return;
    const int e = i * 4, h = e % H, tb = e / H, b = tb % B, t = tb / B;
    float4 xv = ((const float4*)x)[i];
    float4 rv = *(const float4*)(r + b * H + h);
    const size_t o = ((size_t)b * T + t) * H + h;
    *(uint32_t*)(dst + o)     = pack_h2(__float2half_rn(xv.x * rv.x), __float2half_rn(xv.y * rv.y));
    *(uint32_t*)(dst + o + 2) = pack_h2(__float2half_rn(xv.z * rv.z), __float2half_rn(xv.w * rv.w));
}

__global__ __launch_bounds__(256) void prep_weights_kernel(
    const float* __restrict__ wq, const float* __restrict__ wkv, const float* __restrict__ wo,
    __half* __restrict__ dq, __half* __restrict__ dkv, __half* __restrict__ dwo)
{
    const int i = blockIdx.x * blockDim.x + threadIdx.x;
    constexpr int NQ = H * H / 4, NKV = 2 * H * H / 4;
    const float* src; __half* dst; int j;
    if (i < NQ)            { src = wq;  dst = dq;  j = i; }
    else if (i < NQ + NKV) { src = wkv; dst = dkv; j = i - NQ; }
    else                   { src = wo;  dst = dwo; j = i - NQ - NKV; }
    float4 xv = ((const float4*)src)[j];
    const size_t o = (size_t)j * 4;
    *(uint32_t*)(dst + o)     = pack_h2(__float2half_rn(xv.x), __float2half_rn(xv.y));
    *(uint32_t*)(dst + o + 2) = pack_h2(__float2half_rn(xv.z), __float2half_rn(xv.w));
}

// ---------------------------------------------------------------------------
// GEMM (single-pass fp16): C = A W^T; epi C = (C*s[n]+bias[n])*outScale.
// Output: fp32 (Cf) or fp16 hi/lo (Chi/Clo) or fp16 single (Chi only).
// 128x128 tile, K-chunk 32, 4-stage cp.async pipeline (20KB/stage, 80KB),
// 2 CTAs/SM, one __syncthreads per chunk.
// ---------------------------------------------------------------------------
namespace {
constexpr int GSTR = 80;                 // 64B data + 16B pad
constexpr int GTILE = 128 * GSTR;        // 10240
constexpr int GSTAGE = 2 * GTILE;        // A + W = 20480
constexpr int GEMM_SMEM = 4 * GSTAGE;    // 81920
constexpr int NCH = 32;
}

__global__ __launch_bounds__(256, 2) void gemm_mma_kernel(
    const __half* __restrict__ a_, const __half* __restrict__ w_,
    int Mb,
    float* __restrict__ Cf, __half* __restrict__ Chi, __half* __restrict__ Clo,
    int ldc, long long strideCb,
    const float* __restrict__ svec, int sStride, const float* __restrict__ bias,
    float outScale)
{
    extern __shared__ char smraw[];
    const uint32_t sb = smem_u32(smraw);

    const int tid = threadIdx.x, lane = tid & 31, wid = tid >> 5;
    const int wm = wid & 1, wn = wid >> 1;
    const int n0 = blockIdx.x * 128, m0 = blockIdx.y * 128, z = blockIdx.z;

    const __half* A = a_ + (size_t)z * Mb * K + (size_t)m0 * K;
    const __half* W = w_ + (size_t)n0 * K;

    float acc[4][4][4];
#pragma unroll
    for (int a = 0; a < 4; a++)
#pragma unroll
        for (int b = 0; b < 4; b++)
#pragma unroll
            for (int c = 0; c < 4; c++) acc[a][b][c] = 0.f;

    auto issue_chunk = [&](int c, int st) {
        const uint32_t base = sb + st * GSTAGE;
        const size_t go = (size_t)c * 32;
#pragma unroll
        for (int i = 0; i < 2; i++) {
            const int id = tid + i * 256;            // 0..511
            const int row = id >> 2, cc = id & 3;    // 128 rows x 4 x 16B
            cpa16(base + row * GSTR + cc * 16,         A + go + (size_t)row * K + cc * 8);
            cpa16(base + GTILE + row * GSTR + cc * 16, W + go + (size_t)row * K + cc * 8);
        }
        cpa_commit();
    };

    issue_chunk(0, 0); issue_chunk(1, 1); issue_chunk(2, 2);

#pragma unroll 1
    for (int c = 0; c < NCH; c++) {
        cpa_wait<2>();
        __syncthreads();
        if (c + 3 < NCH) issue_chunk(c + 3, (c + 3) & 3); else cpa_commit();

        const uint32_t bufb = sb + (c & 3) * GSTAGE;
#pragma unroll
        for (int ks = 0; ks < 2; ks++) {
            uint32_t af[4][4];
#pragma unroll
            for (int mt = 0; mt < 4; mt++) {
                const uint32_t ra = bufb +
                    (wm * 64 + mt * 16 + (lane & 15)) * GSTR +
                    ks * 32 + (lane >> 4) * 16;
                ldsm4(af[mt], ra);
            }
#pragma unroll
            for (int nt2 = 0; nt2 < 2; nt2++) {
                const uint32_t rb = bufb + GTILE +
                    (wn * 32 + nt2 * 16 + (lane & 7) + ((lane >> 4) & 1) * 8) * GSTR +
                    ks * 32 + ((lane >> 3) & 1) * 16;
                uint32_t bf[4];
                ldsm4(bf, rb);
#pragma unroll
                for (int mt = 0; mt < 4; mt++) {
                    mma16816h(acc[mt][2 * nt2],     af[mt], bf[0], bf[1]);
                    mma16816h(acc[mt][2 * nt2 + 1], af[mt], bf[2], bf[3]);
                }
            }
        }
    }

    // epilogue
    const long long cb = (long long)z * strideCb;
    const int g = lane >> 2, tq = (lane & 3) * 2;
#pragma unroll
    for (int mt = 0; mt < 4; mt++) {
#pragma unroll
        for (int nt = 0; nt < 4; nt++) {
            const int row0 = m0 + wm * 64 + mt * 16 + g;
            const int col  = n0 + wn * 32 + nt * 8 + tq;
            float sv0 = 1.f, sv1 = 1.f, bv0 = 0.f, bv1 = 0.f;
            if (svec) {
                sv0 = __ldg(svec + (size_t)z * sStride + col);
                sv1 = __ldg(svec + (size_t)z * sStride + col + 1);
            }
            if (bias) { bv0 = __ldg(bias + col); bv1 = __ldg(bias + col + 1); }
            const float v0 = (acc[mt][nt][0] * sv0 + bv0) * outScale;
            const float v1 = (acc[mt][nt][1] * sv1 + bv1) * outScale;
            const float v2 = (acc[mt][nt][2] * sv0 + bv0) * outScale;
            const float v3 = (acc[mt][nt][3] * sv1 + bv1) * outScale;
            const size_t i0 = (size_t)(cb + (long long)row0 * ldc + col);
            const size_t i1 = i0 + (size_t)8 * ldc;
            if (Cf) {
                *(float2*)(Cf + i0) = make_float2(v0, v1);
                *(float2*)(Cf + i1) = make_float2(v2, v3);
            } else if (Clo) {
                uint32_t h, l;
                pack_hilo_h(v0, v1, h, l);
                *(uint32_t*)(Chi + i0) = h; *(uint32_t*)(Clo + i0) = l;
                pack_hilo_h(v2, v3, h, l);
                *(uint32_t*)(Chi + i1) = h; *(uint32_t*)(Clo + i1) = l;
            } else {
                *(uint32_t*)(Chi + i0) = pack_h2(__float2half_rn(v0), __float2half_rn(v1));
                *(uint32_t*)(Chi + i1) = pack_h2(__float2half_rn(v2), __float2half_rn(v3));
            }
        }
    }
}

// ---------------------------------------------------------------------------
// Flash attention, fp16 3-term (error ~2^-24). q-tile 256 per CTA; 8 warps,
// two 16-row strips each; KV blocks of 64 rows, 3-stage cp.async pipeline.
// Q pre-scaled by hd^-0.5*log2(e) in the q-projection epilogue.
// ctx written as single fp16 (consumed by 1-term out projection).
// ---------------------------------------------------------------------------
namespace {
constexpr int KSTR   = 144;
constexpr int QTILE  = 256 * KSTR;                 // 36864 (hi or lo)
constexpr int KTILE  = 64 * KSTR;                  // 9216
constexpr int KSTAGE = 4 * KTILE;                  // Kh,Kl,Vh,Vl = 36864
constexpr int ATTN_SMEM = 2 * QTILE + 3 * KSTAGE;  // 184320
constexpr int NKB = 16;
}

__global__ __launch_bounds__(256, 1) void attn_mma_kernel(
    const __half* __restrict__ qh_, const __half* __restrict__ ql_,
    const __half* __restrict__ kvh_, const __half* __restrict__ kvl_,
    __half* __restrict__ cx)
{
    extern __shared__ char smraw[];
    const uint32_t sb = smem_u32(smraw);
    const uint32_t QH = 0, QL = QTILE, KVB = 2 * QTILE;

    const int tid = threadIdx.x, lane = tid & 31, wid = tid >> 5;
    const int n = blockIdx.y, b = n >> 4, j = n & 15;
    const int q0 = blockIdx.x * 256;

    // ---- issue Q load (256 rows hi+lo, 1 group) ----
    {
        const __half* s0 = qh_ + ((size_t)(b * TQ + q0)) * H + j * 64;
        const __half* s1 = ql_ + ((size_t)(b * TQ + q0)) * H + j * 64;
#pragma unroll
        for (int i = 0; i < 8; i++) {
            const int id = tid + i * 256;
            const int row = id >> 3, cc = id & 7;
            cpa16(sb + QH + row * KSTR + cc * 16, s0 + (size_t)row * H + cc * 8);
            cpa16(sb + QL + row * KSTR + cc * 16, s1 + (size_t)row * H + cc * 8);
        }
        cpa_commit();
    }

    const size_t kvcol = (size_t)j * 128;
    auto issue_kv = [&](int kb, int st) {
        const uint32_t base = sb + KVB + st * KSTAGE;
        const size_t rbase = (size_t)(b * TK + kb * 64);
#pragma unroll
        for (int i = 0; i < 2; i++) {
            const int id = tid + i * 256;
            const int row = id >> 3, cc = id & 7;
            const size_t gsrc = (rbase + row) * 2048 + kvcol + cc * 8;
            const uint32_t sof = base + row * KSTR + cc * 16;
            cpa16(sof,             kvh_ + gsrc);
            cpa16(sof + KTILE,     kvl_ + gsrc);
            cpa16(sof + 2 * KTILE, kvh_ + gsrc + 64);
            cpa16(sof + 3 * KTILE, kvl_ + gsrc + 64);
        }
        cpa_commit();
    };
    issue_kv(0, 0);
    issue_kv(1, 1);

    // ---- Q fragments to registers (2 strips, hi+lo) ----
    cpa_wait<2>();
    __syncthreads();
    uint32_t qfh[2][4][4], qfl[2][4][4];
#pragma unroll
    for (int s = 0; s < 2; s++)
#pragma unroll
        for (int kt = 0; kt < 4; kt++) {
            const uint32_t ra = sb + QH +
                (s * 128 + wid * 16 + (lane & 15)) * KSTR +
                kt * 32 + (lane >> 4) * 16;
            ldsm4(qfh[s][kt], ra);
            ldsm4(qfl[s][kt], ra + QTILE);
        }

    float O[2][8][4];
#pragma unroll
    for (int s = 0; s < 2; s++)
#pragma unroll
        for (int d = 0; d < 8; d++)
#pragma unroll
            for (int e = 0; e < 4; e++) O[s][d][e] = 0.f;
    float mrow[2][2] = {{-1e30f, -1e30f}, {-1e30f, -1e30f}};
    float lrow[2][2] = {{0.f, 0.f}, {0.f, 0.f}};

    uint32_t ph[2][4][4], pl[2][4][4];

    for (int kb = 0; kb < NKB; kb++) {
        cpa_wait<1>();
        __syncthreads();
        if (kb + 2 < NKB) issue_kv(kb + 2, (kb + 2) % 3); else cpa_commit();

        const uint32_t stg = sb + KVB + (kb % 3) * KSTAGE;

#pragma unroll
        for (int s = 0; s < 2; s++) {
            float S[8][4];
#pragma unroll
            for (int t = 0; t < 8; t++)
#pragma unroll
                for (int e = 0; e < 4; e++) S[t][e] = 0.f;

#pragma unroll
            for (int nt2 = 0; nt2 < 4; nt2++) {
#pragma unroll
                for (int dt = 0; dt < 4; dt++) {
                    const uint32_t rb = stg +
                        (nt2 * 16 + (lane & 7) + ((lane >> 4) & 1) * 8) * KSTR +
                        dt * 32 + ((lane >> 3) & 1) * 16;
                    uint32_t bh[4], bl[4];
                    ldsm4(bh, rb);
                    ldsm4(bl, rb + KTILE);
                    mma16816h(S[2 * nt2],     qfh[s][dt], bh[0], bh[1]);
                    mma16816h(S[2 * nt2],     qfh[s][dt], bl[0], bl[1]);
                    mma16816h(S[2 * nt2],     qfl[s][dt], bh[0], bh[1]);
                    mma16816h(S[2 * nt2 + 1], qfh[s][dt], bh[2], bh[3]);
                    mma16816h(S[2 * nt2 + 1], qfh[s][dt], bl[2], bl[3]);
                    mma16816h(S[2 * nt2 + 1], qfl[s][dt], bh[2], bh[3]);
                }
            }

            // online softmax (log2 units; Q pre-scaled)
            float mx0 = -1e30f, mx1 = -1e30f;
#pragma unroll
            for (int t = 0; t < 8; t++) {
                mx0 = fmaxf(mx0, fmaxf(S[t][0], S[t][1]));
                mx1 = fmaxf(mx1, fmaxf(S[t][2], S[t][3]));
            }
            mx0 = fmaxf(mx0, __shfl_xor_sync(0xffffffffu, mx0, 1));
            mx0 = fmaxf(mx0, __shfl_xor_sync(0xffffffffu, mx0, 2));
            mx1 = fmaxf(mx1, __shfl_xor_sync(0xffffffffu, mx1, 1));
            mx1 = fmaxf(mx1, __shfl_xor_sync(0xffffffffu, mx1, 2));
            const float mn0 = fmaxf(mrow[s][0], mx0), mn1 = fmaxf(mrow[s][1], mx1);
            const float c0 = ex2(mrow[s][0] - mn0), c1 = ex2(mrow[s][1] - mn1);
            mrow[s][0] = mn0; mrow[s][1] = mn1;

            float sum0 = 0.f, sum1 = 0.f;
#pragma unroll
            for (int t = 0; t < 8; t++) {
                S[t][0] = ex2(S[t][0] - mn0); S[t][1] = ex2(S[t][1] - mn0);
                S[t][2] = ex2(S[t][2] - mn1); S[t][3] = ex2(S[t][3] - mn1);
                sum0 += S[t][0] + S[t][1];
                sum1 += S[t][2] + S[t][3];
            }
            sum0 += __shfl_xor_sync(0xffffffffu, sum0, 1);
            sum0 += __shfl_xor_sync(0xffffffffu, sum0, 2);
            sum1 += __shfl_xor_sync(0xffffffffu, sum1, 1);
            sum1 += __shfl_xor_sync(0xffffffffu, sum1, 2);
            lrow[s][0] = lrow[s][0] * c0 + sum0;
            lrow[s][1] = lrow[s][1] * c1 + sum1;
#pragma unroll
            for (int d = 0; d < 8; d++) {
                O[s][d][0] *= c0; O[s][d][1] *= c0; O[s][d][2] *= c1; O[s][d][3] *= c1;
            }

#pragma unroll
            for (int kk = 0; kk < 4; kk++) {
                pack_hilo_h(S[2 * kk][0],     S[2 * kk][1],     ph[s][kk][0], pl[s][kk][0]);
                pack_hilo_h(S[2 * kk][2],     S[2 * kk][3],     ph[s][kk][1], pl[s][kk][1]);
                pack_hilo_h(S[2 * kk + 1][0], S[2 * kk + 1][1], ph[s][kk][2], pl[s][kk][2]);
                pack_hilo_h(S[2 * kk + 1][2], S[2 * kk + 1][3], ph[s][kk][3], pl[s][kk][3]);
            }
        }

        // ---- O += P V (3-term), V fragments shared by both strips ----
#pragma unroll
        for (int kk = 0; kk < 4; kk++) {
#pragma unroll
            for (int dt2 = 0; dt2 < 4; dt2++) {
                const uint32_t rv = stg + 2 * KTILE +
                    (kk * 16 + (lane & 15)) * KSTR +
                    dt2 * 32 + (lane >> 4) * 16;
                uint32_t vh[4], vl[4];
                ldsm4t(vh, rv);
                ldsm4t(vl, rv + KTILE);
#pragma unroll
                for (int s = 0; s < 2; s++) {
                    mma16816h(O[s][2 * dt2],     ph[s][kk], vh[0], vh[1]);
                    mma16816h(O[s][2 * dt2],     pl[s][kk], vh[0], vh[1]);
                    mma16816h(O[s][2 * dt2],     ph[s][kk], vl[0], vl[1]);
                    mma16816h(O[s][2 * dt2 + 1], ph[s][kk], vh[2], vh[3]);
                    mma16816h(O[s][2 * dt2 + 1], pl[s][kk], vh[2], vh[3]);
                    mma16816h(O[s][2 * dt2 + 1], ph[s][kk], vl[2], vl[3]);
                }
            }
        }
    }

    // ---- epilogue: single fp16 ctx ----
    const int g = lane >> 2, tq = (lane & 3) * 2;
#pragma unroll
    for (int s = 0; s < 2; s++) {
        const float i0 = 1.f / lrow[s][0], i1 = 1.f / lrow[s][1];
        const int t0 = q0 + s * 128 + wid * 16 + g;
#pragma unroll
        for (int d = 0; d < 8; d++) {
            const int hcol = j * 64 + d * 8 + tq;
            const size_t idx0 = ((size_t)t0 * B + b) * H + hcol;
            const size_t idx1 = ((size_t)(t0 + 8) * B + b) * H + hcol;
            *(uint32_t*)(cx + idx0) =
                pack_h2(__float2half_rn(O[s][d][0] * i0), __float2half_rn(O[s][d][1] * i0));
            *(uint32_t*)(cx + idx1) =
                pack_h2(__float2half_rn(O[s][d][2] * i1), __float2half_rn(O[s][d][3] * i1));
        }
    }
}

// ---------------------------------------------------------------------------
extern "C" void kernel_launch(void* const* d_in, const int* in_sizes, int n_in,
                              void* d_out, int out_size)
{
    const float* inputs_q  = (const float*)d_in[0];
    const float* inputs_kv = (const float*)d_in[1];
    const float* w_q  = (const float*)d_in[2];
    const float* b_q  = (const float*)d_in[3];
    const float* w_kv = (const float*)d_in[4];
    const float* b_kv = (const float*)d_in[5];
    const float* w_o  = (const float*)d_in[6];
    const float* b_o  = (const float*)d_in[7];
    const float* r_q  = (const float*)d_in[8];
    const float* s_q  = (const float*)d_in[9];
    const float* r_kv = (const float*)d_in[10];
    const float* s_kv = (const float*)d_in[11];
    float* out = (float*)d_out;

    void* p;
    cudaGetSymbolAddress(&p, g_aq);   __half* aq  = (__half*)p;
    cudaGetSymbolAddress(&p, g_akv);  __half* akv = (__half*)p;
    cudaGetSymbolAddress(&p, g_wq);   __half* wq  = (__half*)p;
    cudaGetSymbolAddress(&p, g_wkv);  __half* wkv = (__half*)p;
    cudaGetSymbolAddress(&p, g_wo);   __half* wo  = (__half*)p;
    cudaGetSymbolAddress(&p, g_qh);   __half* qh  = (__half*)p;
    cudaGetSymbolAddress(&p, g_ql);   __half* ql  = (__half*)p;
    cudaGetSymbolAddress(&p, g_kvh);  __half* kvh = (__half*)p;
    cudaGetSymbolAddress(&p, g_kvl);  __half* kvl = (__half*)p;
    cudaGetSymbolAddress(&p, g_cx);   __half* cx  = (__half*)p;

    cudaFuncSetAttribute(gemm_mma_kernel, cudaFuncAttributeMaxDynamicSharedMemorySize, GEMM_SMEM);
    cudaFuncSetAttribute(attn_mma_kernel, cudaFuncAttributeMaxDynamicSharedMemorySize, ATTN_SMEM);

    const float SCALE = 0.125f * 1.44269504f;   // hd^-0.5 * log2(e)

    const int act4 = TQ * B * H / 4;
    prep_act_kernel<<<(act4 + 255) / 256, 256>>>(inputs_q,  r_q,  aq,  TQ);
    prep_act_kernel<<<(act4 + 255) / 256, 256>>>(inputs_kv, r_kv, akv, TK);
    prep_weights_kernel<<<(H * H + 255) / 256, 256>>>(w_q, w_kv, w_o, wq, wkv, wo);

    // q projection -> fp16 hi/lo q [b][t][H], pre-scaled for softmax
    gemm_mma_kernel<<<dim3(8, 8, 8), 256, GEMM_SMEM>>>(
        aq, wq, TQ, nullptr, qh, ql,
        H, (long long)TQ * H, s_q, H, b_q, SCALE);

    // kv projection -> fp16 hi/lo kv [b][t][2H]
    gemm_mma_kernel<<<dim3(16, 8, 8), 256, GEMM_SMEM>>>(
        akv, wkv, TK, nullptr, kvh, kvl,
        2 * H, (long long)TK * 2 * H, s_kv, 2 * H, b_kv, 1.0f);

    // attention -> ctx single fp16 [t][b][H]
    attn_mma_kernel<<<dim3(4, 128), 256, ATTN_SMEM>>>(qh, ql, kvh, kvl, cx);

    // output projection -> fp32 out
    gemm_mma_kernel<<<dim3(8, 64, 1), 256, GEMM_SMEM>>>(
        cx, wo, TQ * B, out, nullptr, nullptr,
        H, 0LL, nullptr, 0, b_o, 1.0f);
}

// round 7
// speedup vs baseline: 2.8725x; 1.6040x over previous
#include <cuda_runtime.h>
#include <cuda_fp16.h>
#include <cstdint>

// ---------------------------------------------------------------------------
// BEEncdecMultiheadAttn: Tq=Tk=1024, B=8, H=1024, heads=16, hd=64
// Round 7: all-fp16 single-precision pipeline (projections AND attention).
// GEMM: K-chunk 64, 2-stage cp.async, 2 CTAs/SM. Attention: q-tile 128,
// 3-stage KV pipeline, 2 CTAs/SM, single-fp16 Q/K/P/V.
// ---------------------------------------------------------------------------

namespace {
constexpr int TQ = 1024, TK = 1024, B = 8, H = 1024, K = 1024;
}

// scratch (device globals: allocation-free)
__device__ __half g_aq [B * TQ * H];        // activations q  [b][t][H]
__device__ __half g_akv[B * TK * H];        // activations kv [b][t][H]
__device__ __half g_wq [H * H];
__device__ __half g_wkv[2 * H * H];
__device__ __half g_wo [H * H];
__device__ __half g_q  [B * TQ * H];        // q  [b][t][H]  (pre-scaled)
__device__ __half g_kv [B * TK * 2 * H];    // kv [b][t][2H]
__device__ __half g_cx [TQ * B * H];        // ctx [t][b][H]

// ---------------------------------------------------------------------------
// helpers (sm_80+ baseline PTX only)
// ---------------------------------------------------------------------------
__device__ __forceinline__ uint32_t smem_u32(const void* p) {
    uint32_t a;
    asm("{ .reg .u64 t; cvta.to.shared.u64 t, %1; cvt.u32.u64 %0, t; }" : "=r"(a) : "l"(p));
    return a;
}
__device__ __forceinline__ void cpa16(uint32_t dst, const void* src) {
    asm volatile("cp.async.cg.shared.global [%0], [%1], 16;" :: "r"(dst), "l"(src));
}
__device__ __forceinline__ void cpa_commit() { asm volatile("cp.async.commit_group;" ::: "memory"); }
template <int N>
__device__ __forceinline__ void cpa_wait() { asm volatile("cp.async.wait_group %0;" :: "n"(N) : "memory"); }

__device__ __forceinline__ void ldsm4(uint32_t r[4], uint32_t addr) {
    asm volatile("ldmatrix.sync.aligned.m8n8.x4.shared.b16 {%0,%1,%2,%3}, [%4];"
                 : "=r"(r[0]), "=r"(r[1]), "=r"(r[2]), "=r"(r[3]) : "r"(addr));
}
__device__ __forceinline__ void ldsm4t(uint32_t r[4], uint32_t addr) {
    asm volatile("ldmatrix.sync.aligned.m8n8.x4.trans.shared.b16 {%0,%1,%2,%3}, [%4];"
                 : "=r"(r[0]), "=r"(r[1]), "=r"(r[2]), "=r"(r[3]) : "r"(addr));
}
__device__ __forceinline__ void mma16816h(float c[4], const uint32_t a[4], uint32_t b0, uint32_t b1) {
    asm volatile(
        "mma.sync.aligned.m16n8k16.row.col.f32.f16.f16.f32 "
        "{%0,%1,%2,%3}, {%4,%5,%6,%7}, {%8,%9}, {%0,%1,%2,%3};"
        : "+f"(c[0]), "+f"(c[1]), "+f"(c[2]), "+f"(c[3])
        : "r"(a[0]), "r"(a[1]), "r"(a[2]), "r"(a[3]), "r"(b0), "r"(b1));
}
__device__ __forceinline__ float ex2(float x) {
    float y; asm("ex2.approx.ftz.f32 %0, %1;" : "=f"(y) : "f"(x)); return y;
}
__device__ __forceinline__ uint32_t pack_h2(__half x, __half y) {
    __half2 t = __halves2half2(x, y);
    return *reinterpret_cast<uint32_t*>(&t);
}
__device__ __forceinline__ uint32_t pack_f2h(float a, float b) {
    return pack_h2(__float2half_rn(a), __float2half_rn(b));
}

// ---------------------------------------------------------------------------
// prep kernels: fp32 -> fp16 (with r-scale for activations)
// ---------------------------------------------------------------------------
__global__ __launch_bounds__(256) void prep_act_kernel(
    const float* __restrict__ x, const float* __restrict__ r,
    __half* __restrict__ dst, int T)
{
    const int i = blockIdx.x * blockDim.x + threadIdx.x;
    if (i >= T * B * H / 4) return;
    const int e = i * 4, h = e % H, tb = e / H, b = tb % B, t = tb / B;
    float4 xv = ((const float4*)x)[i];
    float4 rv = *(const float4*)(r + b * H + h);
    const size_t o = ((size_t)b * T + t) * H + h;
    *(uint32_t*)(dst + o)     = pack_f2h(xv.x * rv.x, xv.y * rv.y);
    *(uint32_t*)(dst + o + 2) = pack_f2h(xv.z * rv.z, xv.w * rv.w);
}

__global__ __launch_bounds__(256) void prep_weights_kernel(
    const float* __restrict__ wq, const float* __restrict__ wkv, const float* __restrict__ wo,
    __half* __restrict__ dq, __half* __restrict__ dkv, __half* __restrict__ dwo)
{
    const int i = blockIdx.x * blockDim.x + threadIdx.x;
    constexpr int NQ = H * H / 4, NKV = 2 * H * H / 4;
    const float* src; __half* dst; int j;
    if (i < NQ)            { src = wq;  dst = dq;  j = i; }
    else if (i < NQ + NKV) { src = wkv; dst = dkv; j = i - NQ; }
    else                   { src = wo;  dst = dwo; j = i - NQ - NKV; }
    float4 xv = ((const float4*)src)[j];
    const size_t o = (size_t)j * 4;
    *(uint32_t*)(dst + o)     = pack_f2h(xv.x, xv.y);
    *(uint32_t*)(dst + o + 2) = pack_f2h(xv.z, xv.w);
}

// ---------------------------------------------------------------------------
// GEMM (fp16): C = A W^T; epi C = (C*s[n]+bias[n])*outScale.
// 128x128 tile, K-chunk 64, 2-stage cp.async (36KB/stage, 72KB), 2 CTAs/SM,
// one __syncthreads per chunk (16 chunks).
// ---------------------------------------------------------------------------
namespace {
constexpr int GSTR = 144;                // 128B data + 16B pad
constexpr int GTILE = 128 * GSTR;        // 18432
constexpr int GSTAGE = 2 * GTILE;        // A + W = 36864
constexpr int GEMM_SMEM = 2 * GSTAGE;    // 73728
constexpr int NCH = 16;                  // K / 64
}

__global__ __launch_bounds__(256, 2) void gemm_mma_kernel(
    const __half* __restrict__ a_, const __half* __restrict__ w_,
    int Mb,
    float* __restrict__ Cf, __half* __restrict__ Ch,
    int ldc, long long strideCb,
    const float* __restrict__ svec, int sStride, const float* __restrict__ bias,
    float outScale)
{
    extern __shared__ char smraw[];
    const uint32_t sb = smem_u32(smraw);

    const int tid = threadIdx.x, lane = tid & 31, wid = tid >> 5;
    const int wm = wid & 1, wn = wid >> 1;
    const int n0 = blockIdx.x * 128, m0 = blockIdx.y * 128, z = blockIdx.z;

    const __half* A = a_ + (size_t)z * Mb * K + (size_t)m0 * K;
    const __half* W = w_ + (size_t)n0 * K;

    float acc[4][4][4];
#pragma unroll
    for (int a = 0; a < 4; a++)
#pragma unroll
        for (int b = 0; b < 4; b++)
#pragma unroll
            for (int c = 0; c < 4; c++) acc[a][b][c] = 0.f;

    auto issue_chunk = [&](int c, int st) {
        const uint32_t base = sb + st * GSTAGE;
        const size_t go = (size_t)c * 64;
#pragma unroll
        for (int i = 0; i < 4; i++) {
            const int id = tid + i * 256;            // 0..1023
            const int row = id >> 3, cc = id & 7;    // 128 rows x 8 x 16B
            cpa16(base + row * GSTR + cc * 16,         A + go + (size_t)row * K + cc * 8);
            cpa16(base + GTILE + row * GSTR + cc * 16, W + go + (size_t)row * K + cc * 8);
        }
        cpa_commit();
    };

    issue_chunk(0, 0);

#pragma unroll 1
    for (int c = 0; c < NCH; c++) {
        cpa_wait<0>();
        __syncthreads();
        if (c + 1 < NCH) issue_chunk(c + 1, (c + 1) & 1);

        const uint32_t bufb = sb + (c & 1) * GSTAGE;
#pragma unroll
        for (int ks = 0; ks < 4; ks++) {
            uint32_t af[4][4];
#pragma unroll
            for (int mt = 0; mt < 4; mt++) {
                const uint32_t ra = bufb +
                    (wm * 64 + mt * 16 + (lane & 15)) * GSTR +
                    ks * 32 + (lane >> 4) * 16;
                ldsm4(af[mt], ra);
            }
#pragma unroll
            for (int nt2 = 0; nt2 < 2; nt2++) {
                const uint32_t rb = bufb + GTILE +
                    (wn * 32 + nt2 * 16 + (lane & 7) + ((lane >> 4) & 1) * 8) * GSTR +
                    ks * 32 + ((lane >> 3) & 1) * 16;
                uint32_t bf[4];
                ldsm4(bf, rb);
#pragma unroll
                for (int mt = 0; mt < 4; mt++) {
                    mma16816h(acc[mt][2 * nt2],     af[mt], bf[0], bf[1]);
                    mma16816h(acc[mt][2 * nt2 + 1], af[mt], bf[2], bf[3]);
                }
            }
        }
    }

    // epilogue
    const long long cb = (long long)z * strideCb;
    const int g = lane >> 2, tq = (lane & 3) * 2;
#pragma unroll
    for (int mt = 0; mt < 4; mt++) {
#pragma unroll
        for (int nt = 0; nt < 4; nt++) {
            const int row0 = m0 + wm * 64 + mt * 16 + g;
            const int col  = n0 + wn * 32 + nt * 8 + tq;
            float sv0 = 1.f, sv1 = 1.f, bv0 = 0.f, bv1 = 0.f;
            if (svec) {
                sv0 = __ldg(svec + (size_t)z * sStride + col);
                sv1 = __ldg(svec + (size_t)z * sStride + col + 1);
            }
            if (bias) { bv0 = __ldg(bias + col); bv1 = __ldg(bias + col + 1); }
            const float v0 = (acc[mt][nt][0] * sv0 + bv0) * outScale;
            const float v1 = (acc[mt][nt][1] * sv1 + bv1) * outScale;
            const float v2 = (acc[mt][nt][2] * sv0 + bv0) * outScale;
            const float v3 = (acc[mt][nt][3] * sv1 + bv1) * outScale;
            const size_t i0 = (size_t)(cb + (long long)row0 * ldc + col);
            const size_t i1 = i0 + (size_t)8 * ldc;
            if (Cf) {
                *(float2*)(Cf + i0) = make_float2(v0, v1);
                *(float2*)(Cf + i1) = make_float2(v2, v3);
            } else {
                *(uint32_t*)(Ch + i0) = pack_f2h(v0, v1);
                *(uint32_t*)(Ch + i1) = pack_f2h(v2, v3);
            }
        }
    }
}

// ---------------------------------------------------------------------------
// Flash attention, single fp16 everywhere. Block = (q-tile 128, head-batch n),
// 8 warps x 16 q-rows; KV blocks of 64 rows, 3-stage cp.async pipeline,
// 2 CTAs/SM. Q pre-scaled by hd^-0.5*log2(e).
// ---------------------------------------------------------------------------
namespace {
constexpr int KSTR   = 144;
constexpr int QTILE  = 128 * KSTR;                 // 18432
constexpr int KTILE  = 64 * KSTR;                  // 9216 (K or V)
constexpr int KSTAGE = 2 * KTILE;                  // K + V = 18432
constexpr int ATTN_SMEM = QTILE + 3 * KSTAGE;      // 73728
constexpr int NKB = 16;
}

__global__ __launch_bounds__(256, 2) void attn_mma_kernel(
    const __half* __restrict__ q_, const __half* __restrict__ kv_,
    __half* __restrict__ cx)
{
    extern __shared__ char smraw[];
    const uint32_t sb = smem_u32(smraw);
    const uint32_t KVB = QTILE;

    const int tid = threadIdx.x, lane = tid & 31, wid = tid >> 5;
    const int n = blockIdx.y, b = n >> 4, j = n & 15;
    const int q0 = blockIdx.x * 128;

    // ---- issue Q load (128 rows, 1 group) ----
    {
        const __half* s0 = q_ + ((size_t)(b * TQ + q0)) * H + j * 64;
#pragma unroll
        for (int i = 0; i < 4; i++) {
            const int id = tid + i * 256;
            const int row = id >> 3, cc = id & 7;
            cpa16(sb + row * KSTR + cc * 16, s0 + (size_t)row * H + cc * 8);
        }
        cpa_commit();
    }

    const size_t kvcol = (size_t)j * 128;
    auto issue_kv = [&](int kb, int st) {
        const uint32_t base = sb + KVB + st * KSTAGE;
        const size_t rbase = (size_t)(b * TK + kb * 64);
#pragma unroll
        for (int i = 0; i < 2; i++) {
            const int id = tid + i * 256;
            const int row = id >> 3, cc = id & 7;
            const size_t gsrc = (rbase + row) * 2048 + kvcol + cc * 8;
            const uint32_t sof = base + row * KSTR + cc * 16;
            cpa16(sof,         kv_ + gsrc);        // K
            cpa16(sof + KTILE, kv_ + gsrc + 64);   // V
        }
        cpa_commit();
    };
    issue_kv(0, 0);
    issue_kv(1, 1);

    // ---- Q fragments to registers ----
    cpa_wait<2>();
    __syncthreads();
    uint32_t qf[4][4];
#pragma unroll
    for (int kt = 0; kt < 4; kt++) {
        const uint32_t ra = sb + (wid * 16 + (lane & 15)) * KSTR +
                            kt * 32 + (lane >> 4) * 16;
        ldsm4(qf[kt], ra);
    }

    float O[8][4];
#pragma unroll
    for (int d = 0; d < 8; d++)
#pragma unroll
        for (int e = 0; e < 4; e++) O[d][e] = 0.f;
    float mrow0 = -1e30f, mrow1 = -1e30f, lrow0 = 0.f, lrow1 = 0.f;

    for (int kb = 0; kb < NKB; kb++) {
        cpa_wait<1>();
        __syncthreads();
        if (kb + 2 < NKB) issue_kv(kb + 2, (kb + 2) % 3); else cpa_commit();

        const uint32_t stg = sb + KVB + (kb % 3) * KSTAGE;

        // ---- S = Q K^T : 8 n8-tiles ----
        float S[8][4];
#pragma unroll
        for (int t = 0; t < 8; t++)
#pragma unroll
            for (int e = 0; e < 4; e++) S[t][e] = 0.f;

#pragma unroll
        for (int nt2 = 0; nt2 < 4; nt2++) {
#pragma unroll
            for (int dt = 0; dt < 4; dt++) {
                const uint32_t rb = stg +
                    (nt2 * 16 + (lane & 7) + ((lane >> 4) & 1) * 8) * KSTR +
                    dt * 32 + ((lane >> 3) & 1) * 16;
                uint32_t bf[4];
                ldsm4(bf, rb);
                mma16816h(S[2 * nt2],     qf[dt], bf[0], bf[1]);
                mma16816h(S[2 * nt2 + 1], qf[dt], bf[2], bf[3]);
            }
        }

        // ---- online softmax (log2 units; Q pre-scaled) ----
        float mx0 = -1e30f, mx1 = -1e30f;
#pragma unroll
        for (int t = 0; t < 8; t++) {
            mx0 = fmaxf(mx0, fmaxf(S[t][0], S[t][1]));
            mx1 = fmaxf(mx1, fmaxf(S[t][2], S[t][3]));
        }
        mx0 = fmaxf(mx0, __shfl_xor_sync(0xffffffffu, mx0, 1));
        mx0 = fmaxf(mx0, __shfl_xor_sync(0xffffffffu, mx0, 2));
        mx1 = fmaxf(mx1, __shfl_xor_sync(0xffffffffu, mx1, 1));
        mx1 = fmaxf(mx1, __shfl_xor_sync(0xffffffffu, mx1, 2));
        const float mn0 = fmaxf(mrow0, mx0), mn1 = fmaxf(mrow1, mx1);
        const float c0 = ex2(mrow0 - mn0), c1 = ex2(mrow1 - mn1);
        mrow0 = mn0; mrow1 = mn1;

        float sum0 = 0.f, sum1 = 0.f;
#pragma unroll
        for (int t = 0; t < 8; t++) {
            S[t][0] = ex2(S[t][0] - mn0); S[t][1] = ex2(S[t][1] - mn0);
            S[t][2] = ex2(S[t][2] - mn1); S[t][3] = ex2(S[t][3] - mn1);
            sum0 += S[t][0] + S[t][1];
            sum1 += S[t][2] + S[t][3];
        }
        sum0 += __shfl_xor_sync(0xffffffffu, sum0, 1);
        sum0 += __shfl_xor_sync(0xffffffffu, sum0, 2);
        sum1 += __shfl_xor_sync(0xffffffffu, sum1, 1);
        sum1 += __shfl_xor_sync(0xffffffffu, sum1, 2);
        lrow0 = lrow0 * c0 + sum0;
        lrow1 = lrow1 * c1 + sum1;
#pragma unroll
        for (int d = 0; d < 8; d++) {
            O[d][0] *= c0; O[d][1] *= c0; O[d][2] *= c1; O[d][3] *= c1;
        }

        // ---- P -> fp16 A-fragments (registers) ----
        uint32_t pf[4][4];
#pragma unroll
        for (int kk = 0; kk < 4; kk++) {
            pf[kk][0] = pack_f2h(S[2 * kk][0],     S[2 * kk][1]);
            pf[kk][1] = pack_f2h(S[2 * kk][2],     S[2 * kk][3]);
            pf[kk][2] = pack_f2h(S[2 * kk + 1][0], S[2 * kk + 1][1]);
            pf[kk][3] = pack_f2h(S[2 * kk + 1][2], S[2 * kk + 1][3]);
        }

        // ---- O += P V ----
#pragma unroll
        for (int kk = 0; kk < 4; kk++) {
#pragma unroll
            for (int dt2 = 0; dt2 < 4; dt2++) {
                const uint32_t rv = stg + KTILE +
                    (kk * 16 + (lane & 15)) * KSTR +
                    dt2 * 32 + (lane >> 4) * 16;
                uint32_t vf[4];
                ldsm4t(vf, rv);
                mma16816h(O[2 * dt2],     pf[kk], vf[0], vf[1]);
                mma16816h(O[2 * dt2 + 1], pf[kk], vf[2], vf[3]);
            }
        }
    }

    // ---- epilogue: fp16 ctx [t][b][H] ----
    const int g = lane >> 2, tq = (lane & 3) * 2;
    const float i0 = 1.f / lrow0, i1 = 1.f / lrow1;
    const int t0 = q0 + wid * 16 + g;
#pragma unroll
    for (int d = 0; d < 8; d++) {
        const int hcol = j * 64 + d * 8 + tq;
        const size_t idx0 = ((size_t)t0 * B + b) * H + hcol;
        const size_t idx1 = ((size_t)(t0 + 8) * B + b) * H + hcol;
        *(uint32_t*)(cx + idx0) = pack_f2h(O[d][0] * i0, O[d][1] * i0);
        *(uint32_t*)(cx + idx1) = pack_f2h(O[d][2] * i1, O[d][3] * i1);
    }
}

// ---------------------------------------------------------------------------
extern "C" void kernel_launch(void* const* d_in, const int* in_sizes, int n_in,
                              void* d_out, int out_size)
{
    const float* inputs_q  = (const float*)d_in[0];
    const float* inputs_kv = (const float*)d_in[1];
    const float* w_q  = (const float*)d_in[2];
    const float* b_q  = (const float*)d_in[3];
    const float* w_kv = (const float*)d_in[4];
    const float* b_kv = (const float*)d_in[5];
    const float* w_o  = (const float*)d_in[6];
    const float* b_o  = (const float*)d_in[7];
    const float* r_q  = (const float*)d_in[8];
    const float* s_q  = (const float*)d_in[9];
    const float* r_kv = (const float*)d_in[10];
    const float* s_kv = (const float*)d_in[11];
    float* out = (float*)d_out;

    void* p;
    cudaGetSymbolAddress(&p, g_aq);  __half* aq  = (__half*)p;
    cudaGetSymbolAddress(&p, g_akv); __half* akv = (__half*)p;
    cudaGetSymbolAddress(&p, g_wq);  __half* wq  = (__half*)p;
    cudaGetSymbolAddress(&p, g_wkv); __half* wkv = (__half*)p;
    cudaGetSymbolAddress(&p, g_wo);  __half* wo  = (__half*)p;
    cudaGetSymbolAddress(&p, g_q);   __half* q   = (__half*)p;
    cudaGetSymbolAddress(&p, g_kv);  __half* kv  = (__half*)p;
    cudaGetSymbolAddress(&p, g_cx);  __half* cx  = (__half*)p;

    cudaFuncSetAttribute(gemm_mma_kernel, cudaFuncAttributeMaxDynamicSharedMemorySize, GEMM_SMEM);
    cudaFuncSetAttribute(attn_mma_kernel, cudaFuncAttributeMaxDynamicSharedMemorySize, ATTN_SMEM);

    const float SCALE = 0.125f * 1.44269504f;   // hd^-0.5 * log2(e)

    const int act4 = TQ * B * H / 4;
    prep_act_kernel<<<(act4 + 255) / 256, 256>>>(inputs_q,  r_q,  aq,  TQ);
    prep_act_kernel<<<(act4 + 255) / 256, 256>>>(inputs_kv, r_kv, akv, TK);
    prep_weights_kernel<<<(H * H + 255) / 256, 256>>>(w_q, w_kv, w_o, wq, wkv, wo);

    // q projection -> fp16 q [b][t][H], pre-scaled for softmax
    gemm_mma_kernel<<<dim3(8, 8, 8), 256, GEMM_SMEM>>>(
        aq, wq, TQ, nullptr, q,
        H, (long long)TQ * H, s_q, H, b_q, SCALE);

    // kv projection -> fp16 kv [b][t][2H]
    gemm_mma_kernel<<<dim3(16, 8, 8), 256, GEMM_SMEM>>>(
        akv, wkv, TK, nullptr, kv,
        2 * H, (long long)TK * 2 * H, s_kv, 2 * H, b_kv, 1.0f);

    // attention -> ctx fp16 [t][b][H]
    attn_mma_kernel<<<dim3(8, 128), 256, ATTN_SMEM>>>(q, kv, cx);

    // output projection -> fp32 out
    gemm_mma_kernel<<<dim3(8, 64, 1), 256, GEMM_SMEM>>>(
        cx, wo, TQ * B, out, nullptr,
        H, 0LL, nullptr, 0, b_o, 1.0f);
}